// round 1
// baseline (speedup 1.0000x reference)
#include <cuda_runtime.h>
#include <math.h>

#define BB   32
#define HH   64
#define WW   64
#define CC   192
#define DIN  384
#define LL   4096   // HH*WW

// ---------------- scratch (device globals; no runtime alloc) ----------------
__device__ float g_xn [BB * LL * CC];    // layernormed x            (~100.7 MB)
__device__ float g_gm [BB * LL];         // per-pixel mean of xn     (0.5 MB)
__device__ int   g_dir[BB];              // selected direction per batch
__device__ float g_h1 [(size_t)BB * LL * DIN];  // fc1 output         (~201 MB)
__device__ float g_act[(size_t)BB * LL * DIN];  // conv+gelu output   (~201 MB)

// ---------------------------- 1) LayerNorm ----------------------------------
// one warp per pixel (row of 192 channels)
__global__ __launch_bounds__(256) void ln_kernel(const float* __restrict__ x,
                                                 const float* __restrict__ nw,
                                                 const float* __restrict__ nb) {
    int warp = (blockIdx.x * blockDim.x + threadIdx.x) >> 5;
    int lane = threadIdx.x & 31;
    if (warp >= BB * LL) return;
    const float* row = x + (size_t)warp * CC;

    float v[6];
    float s = 0.f;
#pragma unroll
    for (int i = 0; i < 6; i++) { v[i] = row[lane + i * 32]; s += v[i]; }
#pragma unroll
    for (int o = 16; o; o >>= 1) s += __shfl_xor_sync(0xffffffffu, s, o);
    float mu = s * (1.f / CC);

    float q = 0.f;
#pragma unroll
    for (int i = 0; i < 6; i++) { float d = v[i] - mu; q += d * d; }
#pragma unroll
    for (int o = 16; o; o >>= 1) q += __shfl_xor_sync(0xffffffffu, q, o);
    float rsig = rsqrtf(q * (1.f / CC) + 1e-5f);

    float xs = 0.f;
    float* dst = g_xn + (size_t)warp * CC;
#pragma unroll
    for (int i = 0; i < 6; i++) {
        int c = lane + i * 32;
        float xn = (v[i] - mu) * rsig * nw[c] + nb[c];
        dst[c] = xn;
        xs += xn;
    }
#pragma unroll
    for (int o = 16; o; o >>= 1) xs += __shfl_xor_sync(0xffffffffu, xs, o);
    if (lane == 0) g_gm[warp] = xs * (1.f / CC);
}

// ---------------------------- 2) Direction selector --------------------------
__device__ __forceinline__ int refl(int k) {   // padded index (0..65) -> orig (0..63)
    return (k == 0) ? 1 : ((k == 65) ? 62 : (k - 1));
}

__global__ __launch_bounds__(256) void sel_kernel(const float* __restrict__ w1,
                                                  const float* __restrict__ b1,
                                                  const float* __restrict__ w2,
                                                  const float* __restrict__ b2) {
    __shared__ float sg[LL];
    __shared__ float red[256];
    __shared__ float sh_s, sv_s;
    int b = blockIdx.x;
    int tid = threadIdx.x;
    for (int i = tid; i < LL; i += 256) sg[i] = g_gm[b * LL + i];
    __syncthreads();

    // sh: rows r in [0,66) padded, cols j in [0,64): |gp[r][j+2]-gp[r][j]|
    float ssh = 0.f;
    for (int t = tid; t < 66 * 64; t += 256) {
        int r = t >> 6, j = t & 63;
        int rr = refl(r);
        ssh += fabsf(sg[rr * 64 + refl(j + 2)] - sg[rr * 64 + refl(j)]);
    }
    // sv: rows i in [0,64), cols c in [0,66) padded
    float ssv = 0.f;
    for (int t = tid; t < 64 * 66; t += 256) {
        int i = t / 66, c = t % 66;
        int cc = refl(c);
        ssv += fabsf(sg[refl(i + 2) * 64 + cc] - sg[refl(i) * 64 + cc]);
    }

    red[tid] = ssh; __syncthreads();
    for (int s = 128; s > 0; s >>= 1) { if (tid < s) red[tid] += red[tid + s]; __syncthreads(); }
    if (tid == 0) sh_s = red[0] * (1.f / 4224.f);
    __syncthreads();
    red[tid] = ssv; __syncthreads();
    for (int s = 128; s > 0; s >>= 1) { if (tid < s) red[tid] += red[tid + s]; __syncthreads(); }
    if (tid == 0) {
        float sh = sh_s, sv = red[0] * (1.f / 4224.f);
        float sc[4] = { sh, sv, 0.5f * (sh + sv), fabsf(sh - sv) };
        float hid[16];
#pragma unroll
        for (int j = 0; j < 16; j++) {
            float a = b1[j];
#pragma unroll
            for (int k = 0; k < 4; k++) a += sc[k] * w1[j * 4 + k];
            hid[j] = fmaxf(a, 0.f);
        }
        int best = 0; float bv = -1e30f;
#pragma unroll
        for (int i = 0; i < 4; i++) {
            float a = b2[i];
#pragma unroll
            for (int j = 0; j < 16; j++) a += hid[j] * w2[i * 16 + j];
            if (a > bv) { bv = a; best = i; }
        }
        g_dir[b] = best;
    }
}

// ---------------------------- 3) GEMM1: h1 = gather(xn) @ fc1_w^T + b1 -------
// A: [4096 x 192] gathered per-batch by direction; B: fc1_w [384 x 192] row-major
__global__ __launch_bounds__(256) void gemm1_kernel(const float* __restrict__ w1,
                                                    const float* __restrict__ b1) {
    const int b  = blockIdx.z;
    const int m0 = blockIdx.x * 64;
    const int n0 = blockIdx.y * 64;
    const int dir = g_dir[b];
    __shared__ float As[64][68];
    __shared__ float Bs[64][68];
    const int tid = threadIdx.x;
    const int tx = tid & 15, ty = tid >> 4;
    const float* xnb = g_xn + (size_t)b * LL * CC;

    float acc[4][4];
#pragma unroll
    for (int i = 0; i < 4; i++)
#pragma unroll
        for (int j = 0; j < 4; j++) acc[i][j] = 0.f;

    for (int k0 = 0; k0 < CC; k0 += 64) {
        __syncthreads();
#pragma unroll
        for (int i = 0; i < 4; i++) {
            int q   = tid + i * 256;
            int row = q >> 4;
            int kq  = q & 15;
            int l   = m0 + row;
            int pix;
            if (dir == 0)      pix = l;
            else if (dir == 3) pix = ((l & 63) << 6) + 63 - (l >> 6);
            else               pix = ((l & 63) << 6) + (l >> 6);
            float4 av = *(const float4*)(xnb + (size_t)pix * CC + k0 + kq * 4);
            As[kq * 4 + 0][row] = av.x;
            As[kq * 4 + 1][row] = av.y;
            As[kq * 4 + 2][row] = av.z;
            As[kq * 4 + 3][row] = av.w;
            float4 bv = *(const float4*)(w1 + (size_t)(n0 + row) * CC + k0 + kq * 4);
            Bs[kq * 4 + 0][row] = bv.x;
            Bs[kq * 4 + 1][row] = bv.y;
            Bs[kq * 4 + 2][row] = bv.z;
            Bs[kq * 4 + 3][row] = bv.w;
        }
        __syncthreads();
#pragma unroll
        for (int k = 0; k < 64; k++) {
            float4 a4 = *(const float4*)&As[k][ty * 4];
            float4 b4 = *(const float4*)&Bs[k][tx * 4];
            float a[4] = { a4.x, a4.y, a4.z, a4.w };
            float bb[4] = { b4.x, b4.y, b4.z, b4.w };
#pragma unroll
            for (int i = 0; i < 4; i++)
#pragma unroll
                for (int j = 0; j < 4; j++) acc[i][j] += a[i] * bb[j];
        }
    }
    float4 bias = *(const float4*)(b1 + n0 + tx * 4);
    float bia[4] = { bias.x, bias.y, bias.z, bias.w };
#pragma unroll
    for (int i = 0; i < 4; i++) {
        int m = m0 + ty * 4 + i;
        float4 o;
        o.x = acc[i][0] + bia[0];
        o.y = acc[i][1] + bia[1];
        o.z = acc[i][2] + bia[2];
        o.w = acc[i][3] + bia[3];
        *(float4*)(g_h1 + ((size_t)b * LL + m) * DIN + n0 + tx * 4) = o;
    }
}

// ---------------------------- 4) depthwise conv3 + GELU ----------------------
__global__ __launch_bounds__(256) void convgelu_kernel(const float* __restrict__ cw,
                                                       const float* __restrict__ cb) {
    int idx = blockIdx.x * blockDim.x + threadIdx.x;   // over B*L*DIN
    int d = idx % DIN;
    int l = (idx / DIN) & (LL - 1);
    float v = g_h1[idx] * cw[d * 3 + 1] + cb[d];
    if (l > 0)      v += g_h1[idx - DIN] * cw[d * 3 + 0];
    if (l < LL - 1) v += g_h1[idx + DIN] * cw[d * 3 + 2];
    float ge = 0.5f * v * (1.f + erff(v * 0.70710678118654752f));
    g_act[idx] = ge;
}

// ---------------------------- 5) GEMM2 + bias + residual ---------------------
// out[b,l,c] = x[b,l,c] + sum_d act[b,l,d] * fc2_w[c,d] + b2[c]
__global__ __launch_bounds__(256) void gemm2_kernel(const float* __restrict__ w2,
                                                    const float* __restrict__ b2,
                                                    const float* __restrict__ x,
                                                    float* __restrict__ out) {
    const int b  = blockIdx.z;
    const int m0 = blockIdx.x * 64;
    const int n0 = blockIdx.y * 64;
    __shared__ float As[64][68];
    __shared__ float Bs[64][68];
    const int tid = threadIdx.x;
    const int tx = tid & 15, ty = tid >> 4;
    const float* A = g_act + (size_t)b * LL * DIN;

    float acc[4][4];
#pragma unroll
    for (int i = 0; i < 4; i++)
#pragma unroll
        for (int j = 0; j < 4; j++) acc[i][j] = 0.f;

    for (int k0 = 0; k0 < DIN; k0 += 64) {
        __syncthreads();
#pragma unroll
        for (int i = 0; i < 4; i++) {
            int q   = tid + i * 256;
            int row = q >> 4;
            int kq  = q & 15;
            float4 av = *(const float4*)(A + (size_t)(m0 + row) * DIN + k0 + kq * 4);
            As[kq * 4 + 0][row] = av.x;
            As[kq * 4 + 1][row] = av.y;
            As[kq * 4 + 2][row] = av.z;
            As[kq * 4 + 3][row] = av.w;
            float4 bv = *(const float4*)(w2 + (size_t)(n0 + row) * DIN + k0 + kq * 4);
            Bs[kq * 4 + 0][row] = bv.x;
            Bs[kq * 4 + 1][row] = bv.y;
            Bs[kq * 4 + 2][row] = bv.z;
            Bs[kq * 4 + 3][row] = bv.w;
        }
        __syncthreads();
#pragma unroll
        for (int k = 0; k < 64; k++) {
            float4 a4 = *(const float4*)&As[k][ty * 4];
            float4 b4 = *(const float4*)&Bs[k][tx * 4];
            float a[4] = { a4.x, a4.y, a4.z, a4.w };
            float bb[4] = { b4.x, b4.y, b4.z, b4.w };
#pragma unroll
            for (int i = 0; i < 4; i++)
#pragma unroll
                for (int j = 0; j < 4; j++) acc[i][j] += a[i] * bb[j];
        }
    }
    float4 bias = *(const float4*)(b2 + n0 + tx * 4);
    float bia[4] = { bias.x, bias.y, bias.z, bias.w };
#pragma unroll
    for (int i = 0; i < 4; i++) {
        int m = m0 + ty * 4 + i;
        size_t base = ((size_t)b * LL + m) * CC + n0 + tx * 4;
        float4 xv = *(const float4*)(x + base);
        float4 o;
        o.x = acc[i][0] + bia[0] + xv.x;
        o.y = acc[i][1] + bia[1] + xv.y;
        o.z = acc[i][2] + bia[2] + xv.z;
        o.w = acc[i][3] + bia[3] + xv.w;
        *(float4*)(out + base) = o;
    }
}

// ---------------------------------------------------------------------------
extern "C" void kernel_launch(void* const* d_in, const int* in_sizes, int n_in,
                              void* d_out, int out_size) {
    const float* x      = (const float*)d_in[0];
    const float* norm_w = (const float*)d_in[1];
    const float* norm_b = (const float*)d_in[2];
    const float* sel_w1 = (const float*)d_in[3];
    const float* sel_b1 = (const float*)d_in[4];
    const float* sel_w2 = (const float*)d_in[5];
    const float* sel_b2 = (const float*)d_in[6];
    const float* fc1_w  = (const float*)d_in[7];
    const float* fc1_b  = (const float*)d_in[8];
    const float* conv_w = (const float*)d_in[9];
    const float* conv_b = (const float*)d_in[10];
    const float* fc2_w  = (const float*)d_in[11];
    const float* fc2_b  = (const float*)d_in[12];
    float* out = (float*)d_out;

    // 1) LayerNorm: one warp per pixel
    ln_kernel<<<(BB * LL) / 8, 256>>>(x, norm_w, norm_b);
    // 2) direction selector (per-batch)
    sel_kernel<<<BB, 256>>>(sel_w1, sel_b1, sel_w2, sel_b2);
    // 3) fc1 GEMM with per-batch direction gather
    gemm1_kernel<<<dim3(LL / 64, DIN / 64, BB), 256>>>(fc1_w, fc1_b);
    // 4) depthwise conv + gelu
    convgelu_kernel<<<(BB * LL * DIN) / 256, 256>>>(conv_w, conv_b);
    // 5) fc2 GEMM + bias + residual
    gemm2_kernel<<<dim3(LL / 64, CC / 64, BB), 256>>>(fc2_w, fc2_b, x, out);
}

// round 2
// speedup vs baseline: 2.3265x; 2.3265x over previous
#include <cuda_runtime.h>
#include <math.h>

#define BB   32
#define HH   64
#define WW   64
#define CC   192
#define DIN  384
#define LL   4096   // HH*WW

// ---------------- scratch (device globals; no runtime alloc) ----------------
__device__ float g_xn [BB * LL * CC];           // layernormed x
__device__ float g_gm [BB * LL];                // per-pixel mean of xn
__device__ int   g_dir[BB];                     // selected direction per batch
__device__ float g_h1 [(size_t)BB * LL * DIN];  // fc1 output

__device__ __forceinline__ unsigned f2tf32(float x) {
    unsigned y;
    asm("cvt.rna.tf32.f32 %0, %1;" : "=r"(y) : "f"(x));
    return y;
}

__device__ __forceinline__ void mma_tf32(float c[4], const unsigned a[4],
                                         unsigned b0, unsigned b1) {
    asm volatile(
        "mma.sync.aligned.m16n8k8.row.col.f32.tf32.tf32.f32 "
        "{%0,%1,%2,%3}, {%4,%5,%6,%7}, {%8,%9}, {%0,%1,%2,%3};"
        : "+f"(c[0]), "+f"(c[1]), "+f"(c[2]), "+f"(c[3])
        : "r"(a[0]), "r"(a[1]), "r"(a[2]), "r"(a[3]), "r"(b0), "r"(b1));
}

// ---------------------------- 1) LayerNorm ----------------------------------
__global__ __launch_bounds__(256) void ln_kernel(const float* __restrict__ x,
                                                 const float* __restrict__ nw,
                                                 const float* __restrict__ nb) {
    int warp = (blockIdx.x * blockDim.x + threadIdx.x) >> 5;
    int lane = threadIdx.x & 31;
    if (warp >= BB * LL) return;
    const float* row = x + (size_t)warp * CC;

    float v[6];
    float s = 0.f;
#pragma unroll
    for (int i = 0; i < 6; i++) { v[i] = row[lane + i * 32]; s += v[i]; }
#pragma unroll
    for (int o = 16; o; o >>= 1) s += __shfl_xor_sync(0xffffffffu, s, o);
    float mu = s * (1.f / CC);

    float q = 0.f;
#pragma unroll
    for (int i = 0; i < 6; i++) { float d = v[i] - mu; q += d * d; }
#pragma unroll
    for (int o = 16; o; o >>= 1) q += __shfl_xor_sync(0xffffffffu, q, o);
    float rsig = rsqrtf(q * (1.f / CC) + 1e-5f);

    float xs = 0.f;
    float* dst = g_xn + (size_t)warp * CC;
#pragma unroll
    for (int i = 0; i < 6; i++) {
        int c = lane + i * 32;
        float xn = (v[i] - mu) * rsig * nw[c] + nb[c];
        dst[c] = xn;
        xs += xn;
    }
#pragma unroll
    for (int o = 16; o; o >>= 1) xs += __shfl_xor_sync(0xffffffffu, xs, o);
    if (lane == 0) g_gm[warp] = xs * (1.f / CC);
}

// ---------------------------- 2) Direction selector --------------------------
__device__ __forceinline__ int refl(int k) {
    return (k == 0) ? 1 : ((k == 65) ? 62 : (k - 1));
}

__global__ __launch_bounds__(256) void sel_kernel(const float* __restrict__ w1,
                                                  const float* __restrict__ b1,
                                                  const float* __restrict__ w2,
                                                  const float* __restrict__ b2) {
    __shared__ float sg[LL];
    __shared__ float red[256];
    __shared__ float sh_s;
    int b = blockIdx.x;
    int tid = threadIdx.x;
    for (int i = tid; i < LL; i += 256) sg[i] = g_gm[b * LL + i];
    __syncthreads();

    float ssh = 0.f;
    for (int t = tid; t < 66 * 64; t += 256) {
        int r = t >> 6, j = t & 63;
        int rr = refl(r);
        ssh += fabsf(sg[rr * 64 + refl(j + 2)] - sg[rr * 64 + refl(j)]);
    }
    float ssv = 0.f;
    for (int t = tid; t < 64 * 66; t += 256) {
        int i = t / 66, c = t % 66;
        int cc = refl(c);
        ssv += fabsf(sg[refl(i + 2) * 64 + cc] - sg[refl(i) * 64 + cc]);
    }

    red[tid] = ssh; __syncthreads();
    for (int s = 128; s > 0; s >>= 1) { if (tid < s) red[tid] += red[tid + s]; __syncthreads(); }
    if (tid == 0) sh_s = red[0] * (1.f / 4224.f);
    __syncthreads();
    red[tid] = ssv; __syncthreads();
    for (int s = 128; s > 0; s >>= 1) { if (tid < s) red[tid] += red[tid + s]; __syncthreads(); }
    if (tid == 0) {
        float sh = sh_s, sv = red[0] * (1.f / 4224.f);
        float sc[4] = { sh, sv, 0.5f * (sh + sv), fabsf(sh - sv) };
        float hid[16];
#pragma unroll
        for (int j = 0; j < 16; j++) {
            float a = b1[j];
#pragma unroll
            for (int k = 0; k < 4; k++) a += sc[k] * w1[j * 4 + k];
            hid[j] = fmaxf(a, 0.f);
        }
        int best = 0; float bv = -1e30f;
#pragma unroll
        for (int i = 0; i < 4; i++) {
            float a = b2[i];
#pragma unroll
            for (int j = 0; j < 16; j++) a += hid[j] * w2[i * 16 + j];
            if (a > bv) { bv = a; best = i; }
        }
        g_dir[b] = best;
    }
}

// --------------------- 3) GEMM1 (tf32 MMA): h1 = gather(xn) @ fc1_w^T + b ----
// BM=128 BN=128 BK=32, 256 threads (8 warps, 4x2), warp tile 32x64
__global__ __launch_bounds__(256) void gemm1_tc(const float* __restrict__ w1,
                                                const float* __restrict__ b1) {
    const int b  = blockIdx.z;
    const int m0 = blockIdx.x * 128;
    const int n0 = blockIdx.y * 128;
    const int dir = g_dir[b];
    __shared__ unsigned As[128 * 36];
    __shared__ unsigned Bs[128 * 36];
    const int tid = threadIdx.x, lane = tid & 31, wid = tid >> 5;
    const int mw = (wid & 3) * 32, nw = (wid >> 2) * 64;
    const float* xnb = g_xn + (size_t)b * LL * CC;

    float c[2][8][4];
#pragma unroll
    for (int im = 0; im < 2; im++)
#pragma unroll
        for (int jn = 0; jn < 8; jn++)
#pragma unroll
            for (int t = 0; t < 4; t++) c[im][jn][t] = 0.f;

    for (int k0 = 0; k0 < CC; k0 += 32) {
        __syncthreads();
#pragma unroll
        for (int i = 0; i < 4; i++) {
            int q = tid + i * 256;
            int row = q >> 3, c4 = q & 7;
            int l = m0 + row;
            int pix;
            if (dir == 0)      pix = l;
            else if (dir == 3) pix = ((l & 63) << 6) + 63 - (l >> 6);
            else               pix = ((l & 63) << 6) + (l >> 6);
            float4 av = *(const float4*)(xnb + (size_t)pix * CC + k0 + c4 * 4);
            unsigned* d = &As[row * 36 + c4 * 4];
            d[0] = f2tf32(av.x); d[1] = f2tf32(av.y);
            d[2] = f2tf32(av.z); d[3] = f2tf32(av.w);
            float4 bv = *(const float4*)(w1 + (size_t)(n0 + row) * CC + k0 + c4 * 4);
            unsigned* e = &Bs[row * 36 + c4 * 4];
            e[0] = f2tf32(bv.x); e[1] = f2tf32(bv.y);
            e[2] = f2tf32(bv.z); e[3] = f2tf32(bv.w);
        }
        __syncthreads();
#pragma unroll
        for (int kk = 0; kk < 4; kk++) {
            int kc = kk * 8 + (lane & 3);
            unsigned a[2][4];
#pragma unroll
            for (int im = 0; im < 2; im++) {
                int r = mw + im * 16 + (lane >> 2);
                a[im][0] = As[r * 36 + kc];
                a[im][1] = As[(r + 8) * 36 + kc];
                a[im][2] = As[r * 36 + kc + 4];
                a[im][3] = As[(r + 8) * 36 + kc + 4];
            }
#pragma unroll
            for (int jn = 0; jn < 8; jn++) {
                int n = nw + jn * 8 + (lane >> 2);
                unsigned b0 = Bs[n * 36 + kc];
                unsigned b1v = Bs[n * 36 + kc + 4];
#pragma unroll
                for (int im = 0; im < 2; im++) mma_tf32(c[im][jn], a[im], b0, b1v);
            }
        }
    }
#pragma unroll
    for (int im = 0; im < 2; im++) {
        int r0 = m0 + mw + im * 16 + (lane >> 2);
#pragma unroll
        for (int jn = 0; jn < 8; jn++) {
            int col = n0 + nw + jn * 8 + 2 * (lane & 3);
            float bx = __ldg(b1 + col), by = __ldg(b1 + col + 1);
            float2 o0 = { c[im][jn][0] + bx, c[im][jn][1] + by };
            float2 o1 = { c[im][jn][2] + bx, c[im][jn][3] + by };
            *(float2*)(g_h1 + ((size_t)b * LL + r0) * DIN + col) = o0;
            *(float2*)(g_h1 + ((size_t)b * LL + r0 + 8) * DIN + col) = o1;
        }
    }
}

// ------- 4) GEMM2 (tf32 MMA) with fused depthwise-conv3 + exact GELU in A-load
// out = x + gelu(conv(h1)) @ fc2_w^T + b2
// BM=128 BN=192 BK=32, 384 threads (12 warps, 4x3), warp tile 32x64
__global__ __launch_bounds__(384) void gemm2_tc(const float* __restrict__ w2,
                                                const float* __restrict__ b2,
                                                const float* __restrict__ cw,
                                                const float* __restrict__ cb,
                                                const float* __restrict__ x,
                                                float* __restrict__ out) {
    const int b  = blockIdx.z;
    const int m0 = blockIdx.x * 128;
    __shared__ unsigned As[128 * 36];
    __shared__ unsigned Bs[192 * 36];
    const int tid = threadIdx.x, lane = tid & 31, wid = tid >> 5;
    const int mw = (wid & 3) * 32, nw = (wid >> 2) * 64;
    const float* h1b = g_h1 + (size_t)b * LL * DIN;

    float c[2][8][4];
#pragma unroll
    for (int im = 0; im < 2; im++)
#pragma unroll
        for (int jn = 0; jn < 8; jn++)
#pragma unroll
            for (int t = 0; t < 4; t++) c[im][jn][t] = 0.f;

    for (int k0 = 0; k0 < DIN; k0 += 32) {
        __syncthreads();
        // A tile: conv3 + gelu on the fly
        for (int q = tid; q < 1024; q += 384) {
            int row = q >> 3, c4 = q & 7;
            int l = m0 + row;
            int d0 = k0 + c4 * 4;
            const float* hp = h1b + (size_t)l * DIN + d0;
            float4 hc = *(const float4*)hp;
            float4 hm = { 0.f, 0.f, 0.f, 0.f };
            float4 hl = { 0.f, 0.f, 0.f, 0.f };
            if (l > 0)      hm = *(const float4*)(hp - DIN);
            if (l < LL - 1) hl = *(const float4*)(hp + DIN);
            float vm[4] = { hm.x, hm.y, hm.z, hm.w };
            float vc[4] = { hc.x, hc.y, hc.z, hc.w };
            float vl[4] = { hl.x, hl.y, hl.z, hl.w };
            unsigned* dst = &As[row * 36 + c4 * 4];
#pragma unroll
            for (int j = 0; j < 4; j++) {
                int d = d0 + j;
                float v = vc[j] * __ldg(cw + d * 3 + 1) + __ldg(cb + d);
                v += vm[j] * __ldg(cw + d * 3 + 0);
                v += vl[j] * __ldg(cw + d * 3 + 2);
                float ge = 0.5f * v * (1.f + erff(v * 0.70710678118654752f));
                dst[j] = f2tf32(ge);
            }
        }
        // B tile: fc2_w [192 x 384]
        for (int q = tid; q < 1536; q += 384) {
            int row = q >> 3, c4 = q & 7;
            float4 bv = *(const float4*)(w2 + (size_t)row * DIN + k0 + c4 * 4);
            unsigned* e = &Bs[row * 36 + c4 * 4];
            e[0] = f2tf32(bv.x); e[1] = f2tf32(bv.y);
            e[2] = f2tf32(bv.z); e[3] = f2tf32(bv.w);
        }
        __syncthreads();
#pragma unroll
        for (int kk = 0; kk < 4; kk++) {
            int kc = kk * 8 + (lane & 3);
            unsigned a[2][4];
#pragma unroll
            for (int im = 0; im < 2; im++) {
                int r = mw + im * 16 + (lane >> 2);
                a[im][0] = As[r * 36 + kc];
                a[im][1] = As[(r + 8) * 36 + kc];
                a[im][2] = As[r * 36 + kc + 4];
                a[im][3] = As[(r + 8) * 36 + kc + 4];
            }
#pragma unroll
            for (int jn = 0; jn < 8; jn++) {
                int n = nw + jn * 8 + (lane >> 2);
                unsigned b0 = Bs[n * 36 + kc];
                unsigned b1v = Bs[n * 36 + kc + 4];
#pragma unroll
                for (int im = 0; im < 2; im++) mma_tf32(c[im][jn], a[im], b0, b1v);
            }
        }
    }
#pragma unroll
    for (int im = 0; im < 2; im++) {
        int r0 = m0 + mw + im * 16 + (lane >> 2);
#pragma unroll
        for (int jn = 0; jn < 8; jn++) {
            int col = nw + jn * 8 + 2 * (lane & 3);
            float bx = __ldg(b2 + col), by = __ldg(b2 + col + 1);
            size_t base0 = ((size_t)b * LL + r0) * CC + col;
            size_t base1 = ((size_t)b * LL + r0 + 8) * CC + col;
            float2 x0 = *(const float2*)(x + base0);
            float2 x1 = *(const float2*)(x + base1);
            float2 o0 = { c[im][jn][0] + bx + x0.x, c[im][jn][1] + by + x0.y };
            float2 o1 = { c[im][jn][2] + bx + x1.x, c[im][jn][3] + by + x1.y };
            *(float2*)(out + base0) = o0;
            *(float2*)(out + base1) = o1;
        }
    }
}

// ---------------------------------------------------------------------------
extern "C" void kernel_launch(void* const* d_in, const int* in_sizes, int n_in,
                              void* d_out, int out_size) {
    const float* x      = (const float*)d_in[0];
    const float* norm_w = (const float*)d_in[1];
    const float* norm_b = (const float*)d_in[2];
    const float* sel_w1 = (const float*)d_in[3];
    const float* sel_b1 = (const float*)d_in[4];
    const float* sel_w2 = (const float*)d_in[5];
    const float* sel_b2 = (const float*)d_in[6];
    const float* fc1_w  = (const float*)d_in[7];
    const float* fc1_b  = (const float*)d_in[8];
    const float* conv_w = (const float*)d_in[9];
    const float* conv_b = (const float*)d_in[10];
    const float* fc2_w  = (const float*)d_in[11];
    const float* fc2_b  = (const float*)d_in[12];
    float* out = (float*)d_out;

    ln_kernel<<<(BB * LL) / 8, 256>>>(x, norm_w, norm_b);
    sel_kernel<<<BB, 256>>>(sel_w1, sel_b1, sel_w2, sel_b2);
    gemm1_tc<<<dim3(LL / 128, DIN / 128, BB), 256>>>(fc1_w, fc1_b);
    gemm2_tc<<<dim3(LL / 128, 1, BB), 384>>>(fc2_w, fc2_b, conv_w, conv_b, x, out);
}

// round 3
// speedup vs baseline: 3.5687x; 1.5339x over previous
#include <cuda_runtime.h>
#include <math.h>

#define BB   32
#define HH   64
#define WW   64
#define CC   192
#define DIN  384
#define LL   4096   // HH*WW

// ---------------- scratch (device globals; no runtime alloc) ----------------
__device__ float g_xn [BB * LL * CC];           // layernormed x
__device__ float g_gm [BB * LL];                // per-pixel mean of xn
__device__ int   g_dir[BB];                     // selected direction per batch
__device__ float g_h1 [(size_t)BB * LL * DIN];  // fc1 output
__device__ float g_act[(size_t)BB * LL * DIN];  // gelu(conv(h1))

__device__ __forceinline__ void cp16(float* dst, const float* src) {
    unsigned d = (unsigned)__cvta_generic_to_shared(dst);
    asm volatile("cp.async.ca.shared.global [%0], [%1], 16;" :: "r"(d), "l"(src));
}
__device__ __forceinline__ void cp_commit() {
    asm volatile("cp.async.commit_group;");
}
__device__ __forceinline__ void cp_wait0() {
    asm volatile("cp.async.wait_group 0;");
}

__device__ __forceinline__ void mma_tf32(float c[4], const unsigned a[4],
                                         unsigned b0, unsigned b1) {
    asm volatile(
        "mma.sync.aligned.m16n8k8.row.col.f32.tf32.tf32.f32 "
        "{%0,%1,%2,%3}, {%4,%5,%6,%7}, {%8,%9}, {%0,%1,%2,%3};"
        : "+f"(c[0]), "+f"(c[1]), "+f"(c[2]), "+f"(c[3])
        : "r"(a[0]), "r"(a[1]), "r"(a[2]), "r"(a[3]), "r"(b0), "r"(b1));
}

// ---------------------------- 1) LayerNorm ----------------------------------
__global__ __launch_bounds__(256) void ln_kernel(const float* __restrict__ x,
                                                 const float* __restrict__ nw,
                                                 const float* __restrict__ nb) {
    int warp = (blockIdx.x * blockDim.x + threadIdx.x) >> 5;
    int lane = threadIdx.x & 31;
    if (warp >= BB * LL) return;
    const float* row = x + (size_t)warp * CC;

    float v[6];
    float s = 0.f;
#pragma unroll
    for (int i = 0; i < 6; i++) { v[i] = row[lane + i * 32]; s += v[i]; }
#pragma unroll
    for (int o = 16; o; o >>= 1) s += __shfl_xor_sync(0xffffffffu, s, o);
    float mu = s * (1.f / CC);

    float q = 0.f;
#pragma unroll
    for (int i = 0; i < 6; i++) { float d = v[i] - mu; q += d * d; }
#pragma unroll
    for (int o = 16; o; o >>= 1) q += __shfl_xor_sync(0xffffffffu, q, o);
    float rsig = rsqrtf(q * (1.f / CC) + 1e-5f);

    float xs = 0.f;
    float* dst = g_xn + (size_t)warp * CC;
#pragma unroll
    for (int i = 0; i < 6; i++) {
        int c = lane + i * 32;
        float xn = (v[i] - mu) * rsig * nw[c] + nb[c];
        dst[c] = xn;
        xs += xn;
    }
#pragma unroll
    for (int o = 16; o; o >>= 1) xs += __shfl_xor_sync(0xffffffffu, xs, o);
    if (lane == 0) g_gm[warp] = xs * (1.f / CC);
}

// ---------------------------- 2) Direction selector --------------------------
__device__ __forceinline__ int refl(int k) {
    return (k == 0) ? 1 : ((k == 65) ? 62 : (k - 1));
}

__global__ __launch_bounds__(256) void sel_kernel(const float* __restrict__ w1,
                                                  const float* __restrict__ b1,
                                                  const float* __restrict__ w2,
                                                  const float* __restrict__ b2) {
    __shared__ float sg[LL];
    __shared__ float red[256];
    __shared__ float sh_s;
    int b = blockIdx.x;
    int tid = threadIdx.x;
    for (int i = tid; i < LL; i += 256) sg[i] = g_gm[b * LL + i];
    __syncthreads();

    float ssh = 0.f;
    for (int t = tid; t < 66 * 64; t += 256) {
        int r = t >> 6, j = t & 63;
        int rr = refl(r);
        ssh += fabsf(sg[rr * 64 + refl(j + 2)] - sg[rr * 64 + refl(j)]);
    }
    float ssv = 0.f;
    for (int t = tid; t < 64 * 66; t += 256) {
        int i = t / 66, c = t % 66;
        int cc = refl(c);
        ssv += fabsf(sg[refl(i + 2) * 64 + cc] - sg[refl(i) * 64 + cc]);
    }

    red[tid] = ssh; __syncthreads();
    for (int s = 128; s > 0; s >>= 1) { if (tid < s) red[tid] += red[tid + s]; __syncthreads(); }
    if (tid == 0) sh_s = red[0] * (1.f / 4224.f);
    __syncthreads();
    red[tid] = ssv; __syncthreads();
    for (int s = 128; s > 0; s >>= 1) { if (tid < s) red[tid] += red[tid + s]; __syncthreads(); }
    if (tid == 0) {
        float sh = sh_s, sv = red[0] * (1.f / 4224.f);
        float sc[4] = { sh, sv, 0.5f * (sh + sv), fabsf(sh - sv) };
        float hid[16];
#pragma unroll
        for (int j = 0; j < 16; j++) {
            float a = b1[j];
#pragma unroll
            for (int k = 0; k < 4; k++) a += sc[k] * w1[j * 4 + k];
            hid[j] = fmaxf(a, 0.f);
        }
        int best = 0; float bv = -1e30f;
#pragma unroll
        for (int i = 0; i < 4; i++) {
            float a = b2[i];
#pragma unroll
            for (int j = 0; j < 16; j++) a += hid[j] * w2[i * 16 + j];
            if (a > bv) { bv = a; best = i; }
        }
        g_dir[b] = best;
    }
}

// --------------------- 3) GEMM1 (tf32 MMA, double-buffered cp.async) --------
// h1 = gather(xn) @ fc1_w^T + b1 ; BM=128 BN=128 BK=32, 256 threads
#define G1_ASZ (128 * 36)
#define G1_TSZ (2 * G1_ASZ)

__device__ __forceinline__ void g1_load(const float* __restrict__ xnb,
                                        const float* __restrict__ w1,
                                        int m0, int n0, int k0, int dir,
                                        int tid, float* As, float* Bs) {
#pragma unroll
    for (int i = 0; i < 4; i++) {
        int q = tid + i * 256;
        int row = q >> 3, c4 = q & 7;
        int l = m0 + row;
        int pix;
        if (dir == 0)      pix = l;
        else if (dir == 3) pix = ((l & 63) << 6) + 63 - (l >> 6);
        else               pix = ((l & 63) << 6) + (l >> 6);
        cp16(&As[row * 36 + c4 * 4], xnb + (size_t)pix * CC + k0 + c4 * 4);
        cp16(&Bs[row * 36 + c4 * 4], w1 + (size_t)(n0 + row) * CC + k0 + c4 * 4);
    }
}

__global__ __launch_bounds__(256) void gemm1_tc(const float* __restrict__ w1,
                                                const float* __restrict__ b1) {
    extern __shared__ float sm1[];
    const int b  = blockIdx.z;
    const int m0 = blockIdx.x * 128;
    const int n0 = blockIdx.y * 128;
    const int dir = g_dir[b];
    const int tid = threadIdx.x, lane = tid & 31, wid = tid >> 5;
    const int mw = (wid & 3) * 32, nw = (wid >> 2) * 64;
    const float* xnb = g_xn + (size_t)b * LL * CC;

    float c[2][8][4];
#pragma unroll
    for (int im = 0; im < 2; im++)
#pragma unroll
        for (int jn = 0; jn < 8; jn++)
#pragma unroll
            for (int t = 0; t < 4; t++) c[im][jn][t] = 0.f;

    g1_load(xnb, w1, m0, n0, 0, dir, tid, sm1, sm1 + G1_ASZ);
    cp_commit();

    const int NS = CC / 32;   // 6
#pragma unroll 1
    for (int s = 0; s < NS; s++) {
        cp_wait0();
        __syncthreads();
        float* As = sm1 + (s & 1) * G1_TSZ;
        float* Bs = As + G1_ASZ;
        if (s + 1 < NS) {
            float* An = sm1 + ((s + 1) & 1) * G1_TSZ;
            g1_load(xnb, w1, m0, n0, (s + 1) * 32, dir, tid, An, An + G1_ASZ);
            cp_commit();
        }
#pragma unroll
        for (int kk = 0; kk < 4; kk++) {
            int kc = kk * 8 + (lane & 3);
            unsigned a[2][4];
#pragma unroll
            for (int im = 0; im < 2; im++) {
                int r = mw + im * 16 + (lane >> 2);
                a[im][0] = __float_as_uint(As[r * 36 + kc]);
                a[im][1] = __float_as_uint(As[(r + 8) * 36 + kc]);
                a[im][2] = __float_as_uint(As[r * 36 + kc + 4]);
                a[im][3] = __float_as_uint(As[(r + 8) * 36 + kc + 4]);
            }
#pragma unroll
            for (int jn = 0; jn < 8; jn++) {
                int n = nw + jn * 8 + (lane >> 2);
                unsigned b0 = __float_as_uint(Bs[n * 36 + kc]);
                unsigned b1v = __float_as_uint(Bs[n * 36 + kc + 4]);
#pragma unroll
                for (int im = 0; im < 2; im++) mma_tf32(c[im][jn], a[im], b0, b1v);
            }
        }
        __syncthreads();
    }
#pragma unroll
    for (int im = 0; im < 2; im++) {
        int r0 = m0 + mw + im * 16 + (lane >> 2);
#pragma unroll
        for (int jn = 0; jn < 8; jn++) {
            int col = n0 + nw + jn * 8 + 2 * (lane & 3);
            float bx = __ldg(b1 + col), by = __ldg(b1 + col + 1);
            float2 o0 = { c[im][jn][0] + bx, c[im][jn][1] + by };
            float2 o1 = { c[im][jn][2] + bx, c[im][jn][3] + by };
            *(float2*)(g_h1 + ((size_t)b * LL + r0) * DIN + col) = o0;
            *(float2*)(g_h1 + ((size_t)b * LL + r0 + 8) * DIN + col) = o1;
        }
    }
}

// ---------------------------- 4) depthwise conv3 + GELU ----------------------
// block: 384 threads = 96 channel-quads x 4 row-groups; each thread walks 32 rows
__global__ __launch_bounds__(384) void convgelu_kernel(const float* __restrict__ cw,
                                                       const float* __restrict__ cb) {
    const int b  = blockIdx.y;
    const int l0 = blockIdx.x * 128;
    const int tid = threadIdx.x;
    const int d4 = tid % 96;
    const int rg = tid / 96;
    const int ls = l0 + rg * 32;
    const int d0 = d4 * 4;

    float w0[4], w1[4], w2[4], bb[4];
#pragma unroll
    for (int j = 0; j < 4; j++) {
        w0[j] = __ldg(cw + (d0 + j) * 3 + 0);
        w1[j] = __ldg(cw + (d0 + j) * 3 + 1);
        w2[j] = __ldg(cw + (d0 + j) * 3 + 2);
        bb[j] = __ldg(cb + d0 + j);
    }

    const float* base = g_h1 + ((size_t)b * LL) * DIN + d0;
    float* obase = g_act + ((size_t)b * LL) * DIN + d0;

    float4 prev = (ls == 0) ? make_float4(0, 0, 0, 0)
                            : *(const float4*)(base + (size_t)(ls - 1) * DIN);
    float4 cur = *(const float4*)(base + (size_t)ls * DIN);

#pragma unroll 4
    for (int i = 0; i < 32; i++) {
        int l = ls + i;
        float4 nxt = (l == LL - 1) ? make_float4(0, 0, 0, 0)
                                   : *(const float4*)(base + (size_t)(l + 1) * DIN);
        float pv[4] = { prev.x, prev.y, prev.z, prev.w };
        float cv[4] = { cur.x, cur.y, cur.z, cur.w };
        float nv[4] = { nxt.x, nxt.y, nxt.z, nxt.w };
        float4 o;
        float* op = &o.x;
#pragma unroll
        for (int j = 0; j < 4; j++) {
            float v = pv[j] * w0[j] + cv[j] * w1[j] + nv[j] * w2[j] + bb[j];
            op[j] = 0.5f * v * (1.f + erff(v * 0.70710678118654752f));
        }
        *(float4*)(obase + (size_t)l * DIN) = o;
        prev = cur; cur = nxt;
    }
}

// --------- 5) GEMM2 (tf32 MMA, double-buffered): out = x + act @ w2^T + b2 ---
// BM=128 BN=192 BK=32, 384 threads (12 warps, 4x3)
#define G2_ASZ (128 * 36)
#define G2_BSZ (192 * 36)
#define G2_TSZ (G2_ASZ + G2_BSZ)

__device__ __forceinline__ void g2_load(const float* __restrict__ act,
                                        const float* __restrict__ w2,
                                        int m0, int k0, int tid,
                                        float* As, float* Bs) {
#pragma unroll
    for (int i = 0; i < 3; i++) {
        int q = tid + i * 384;
        if (q < 1024) {
            int row = q >> 3, c4 = q & 7;
            cp16(&As[row * 36 + c4 * 4], act + (size_t)(m0 + row) * DIN + k0 + c4 * 4);
        }
    }
#pragma unroll
    for (int i = 0; i < 4; i++) {
        int q = tid + i * 384;
        int row = q >> 3, c4 = q & 7;
        cp16(&Bs[row * 36 + c4 * 4], w2 + (size_t)row * DIN + k0 + c4 * 4);
    }
}

__global__ __launch_bounds__(384) void gemm2_tc(const float* __restrict__ w2,
                                                const float* __restrict__ b2,
                                                const float* __restrict__ x,
                                                float* __restrict__ out) {
    extern __shared__ float sm2[];
    const int b  = blockIdx.z;
    const int m0 = blockIdx.x * 128;
    const int tid = threadIdx.x, lane = tid & 31, wid = tid >> 5;
    const int mw = (wid & 3) * 32, nw = (wid >> 2) * 64;
    const float* act = g_act + (size_t)b * LL * DIN;

    float c[2][8][4];
#pragma unroll
    for (int im = 0; im < 2; im++)
#pragma unroll
        for (int jn = 0; jn < 8; jn++)
#pragma unroll
            for (int t = 0; t < 4; t++) c[im][jn][t] = 0.f;

    g2_load(act, w2, m0, 0, tid, sm2, sm2 + G2_ASZ);
    cp_commit();

    const int NS = DIN / 32;   // 12
#pragma unroll 1
    for (int s = 0; s < NS; s++) {
        cp_wait0();
        __syncthreads();
        float* As = sm2 + (s & 1) * G2_TSZ;
        float* Bs = As + G2_ASZ;
        if (s + 1 < NS) {
            float* An = sm2 + ((s + 1) & 1) * G2_TSZ;
            g2_load(act, w2, m0, (s + 1) * 32, tid, An, An + G2_ASZ);
            cp_commit();
        }
#pragma unroll
        for (int kk = 0; kk < 4; kk++) {
            int kc = kk * 8 + (lane & 3);
            unsigned a[2][4];
#pragma unroll
            for (int im = 0; im < 2; im++) {
                int r = mw + im * 16 + (lane >> 2);
                a[im][0] = __float_as_uint(As[r * 36 + kc]);
                a[im][1] = __float_as_uint(As[(r + 8) * 36 + kc]);
                a[im][2] = __float_as_uint(As[r * 36 + kc + 4]);
                a[im][3] = __float_as_uint(As[(r + 8) * 36 + kc + 4]);
            }
#pragma unroll
            for (int jn = 0; jn < 8; jn++) {
                int n = nw + jn * 8 + (lane >> 2);
                unsigned b0 = __float_as_uint(Bs[n * 36 + kc]);
                unsigned b1v = __float_as_uint(Bs[n * 36 + kc + 4]);
#pragma unroll
                for (int im = 0; im < 2; im++) mma_tf32(c[im][jn], a[im], b0, b1v);
            }
        }
        __syncthreads();
    }
#pragma unroll
    for (int im = 0; im < 2; im++) {
        int r0 = m0 + mw + im * 16 + (lane >> 2);
#pragma unroll
        for (int jn = 0; jn < 8; jn++) {
            int col = nw + jn * 8 + 2 * (lane & 3);
            float bx = __ldg(b2 + col), by = __ldg(b2 + col + 1);
            size_t base0 = ((size_t)b * LL + r0) * CC + col;
            size_t base1 = ((size_t)b * LL + r0 + 8) * CC + col;
            float2 x0 = *(const float2*)(x + base0);
            float2 x1 = *(const float2*)(x + base1);
            float2 o0 = { c[im][jn][0] + bx + x0.x, c[im][jn][1] + by + x0.y };
            float2 o1 = { c[im][jn][2] + bx + x1.x, c[im][jn][3] + by + x1.y };
            *(float2*)(out + base0) = o0;
            *(float2*)(out + base1) = o1;
        }
    }
}

// ---------------------------------------------------------------------------
extern "C" void kernel_launch(void* const* d_in, const int* in_sizes, int n_in,
                              void* d_out, int out_size) {
    const float* x      = (const float*)d_in[0];
    const float* norm_w = (const float*)d_in[1];
    const float* norm_b = (const float*)d_in[2];
    const float* sel_w1 = (const float*)d_in[3];
    const float* sel_b1 = (const float*)d_in[4];
    const float* sel_w2 = (const float*)d_in[5];
    const float* sel_b2 = (const float*)d_in[6];
    const float* fc1_w  = (const float*)d_in[7];
    const float* fc1_b  = (const float*)d_in[8];
    const float* conv_w = (const float*)d_in[9];
    const float* conv_b = (const float*)d_in[10];
    const float* fc2_w  = (const float*)d_in[11];
    const float* fc2_b  = (const float*)d_in[12];
    float* out = (float*)d_out;

    cudaFuncSetAttribute(gemm1_tc, cudaFuncAttributeMaxDynamicSharedMemorySize,
                         2 * G1_TSZ * (int)sizeof(float));
    cudaFuncSetAttribute(gemm2_tc, cudaFuncAttributeMaxDynamicSharedMemorySize,
                         2 * G2_TSZ * (int)sizeof(float));

    ln_kernel<<<(BB * LL) / 8, 256>>>(x, norm_w, norm_b);
    sel_kernel<<<BB, 256>>>(sel_w1, sel_b1, sel_w2, sel_b2);
    gemm1_tc<<<dim3(LL / 128, DIN / 128, BB), 256,
               2 * G1_TSZ * sizeof(float)>>>(fc1_w, fc1_b);
    convgelu_kernel<<<dim3(LL / 128, BB), 384>>>(conv_w, conv_b);
    gemm2_tc<<<dim3(LL / 128, 1, BB), 384,
               2 * G2_TSZ * sizeof(float)>>>(fc2_w, fc2_b, x, out);
}

// round 5
// speedup vs baseline: 3.8703x; 1.0845x over previous
#include <cuda_runtime.h>
#include <cuda_bf16.h>
#include <math.h>

#define BB   32
#define HH   64
#define WW   64
#define CC   192
#define DIN  384
#define LL   4096   // HH*WW

// ---------------- scratch (device globals; no runtime alloc) ----------------
__device__ float g_xn [BB * LL * CC];                     // layernormed x (fp32)
__device__ float g_gm [BB * LL];                          // per-pixel mean of xn
__device__ int   g_dir[BB];                               // direction per batch
__device__ __nv_bfloat16 g_h1 [(size_t)BB * LL * DIN];    // fc1 output (bf16)
__device__ __nv_bfloat16 g_act[(size_t)BB * LL * DIN];    // gelu(conv(h1)) (bf16)
__device__ __nv_bfloat16 g_w2b[CC * DIN];                 // fc2_w in bf16

__device__ __forceinline__ void cp16(void* dst, const void* src) {
    unsigned d = (unsigned)__cvta_generic_to_shared(dst);
    asm volatile("cp.async.ca.shared.global [%0], [%1], 16;" :: "r"(d), "l"(src));
}
__device__ __forceinline__ void cp_commit() {
    asm volatile("cp.async.commit_group;");
}
__device__ __forceinline__ void cp_wait0() {
    asm volatile("cp.async.wait_group 0;");
}

__device__ __forceinline__ void mma_tf32(float c[4], const unsigned a[4],
                                         unsigned b0, unsigned b1) {
    asm volatile(
        "mma.sync.aligned.m16n8k8.row.col.f32.tf32.tf32.f32 "
        "{%0,%1,%2,%3}, {%4,%5,%6,%7}, {%8,%9}, {%0,%1,%2,%3};"
        : "+f"(c[0]), "+f"(c[1]), "+f"(c[2]), "+f"(c[3])
        : "r"(a[0]), "r"(a[1]), "r"(a[2]), "r"(a[3]), "r"(b0), "r"(b1));
}

__device__ __forceinline__ void mma_bf16(float c[4], const unsigned a[4],
                                         unsigned b0, unsigned b1) {
    asm volatile(
        "mma.sync.aligned.m16n8k16.row.col.f32.bf16.bf16.f32 "
        "{%0,%1,%2,%3}, {%4,%5,%6,%7}, {%8,%9}, {%0,%1,%2,%3};"
        : "+f"(c[0]), "+f"(c[1]), "+f"(c[2]), "+f"(c[3])
        : "r"(a[0]), "r"(a[1]), "r"(a[2]), "r"(a[3]), "r"(b0), "r"(b1));
}

// ---------------------------- 1) LayerNorm ----------------------------------
__global__ __launch_bounds__(256) void ln_kernel(const float* __restrict__ x,
                                                 const float* __restrict__ nw,
                                                 const float* __restrict__ nb) {
    int warp = (blockIdx.x * blockDim.x + threadIdx.x) >> 5;
    int lane = threadIdx.x & 31;
    if (warp >= BB * LL) return;
    const float* row = x + (size_t)warp * CC;

    float v[6];
    float s = 0.f;
#pragma unroll
    for (int i = 0; i < 6; i++) { v[i] = row[lane + i * 32]; s += v[i]; }
#pragma unroll
    for (int o = 16; o; o >>= 1) s += __shfl_xor_sync(0xffffffffu, s, o);
    float mu = s * (1.f / CC);

    float q = 0.f;
#pragma unroll
    for (int i = 0; i < 6; i++) { float d = v[i] - mu; q += d * d; }
#pragma unroll
    for (int o = 16; o; o >>= 1) q += __shfl_xor_sync(0xffffffffu, q, o);
    float rsig = rsqrtf(q * (1.f / CC) + 1e-5f);

    float xs = 0.f;
    float* dst = g_xn + (size_t)warp * CC;
#pragma unroll
    for (int i = 0; i < 6; i++) {
        int c = lane + i * 32;
        float xn = (v[i] - mu) * rsig * nw[c] + nb[c];
        dst[c] = xn;
        xs += xn;
    }
#pragma unroll
    for (int o = 16; o; o >>= 1) xs += __shfl_xor_sync(0xffffffffu, xs, o);
    if (lane == 0) g_gm[warp] = xs * (1.f / CC);
}

// ---------------------------- 2) Direction selector --------------------------
__device__ __forceinline__ int refl(int k) {
    return (k == 0) ? 1 : ((k == 65) ? 62 : (k - 1));
}

__global__ __launch_bounds__(256) void sel_kernel(const float* __restrict__ w1,
                                                  const float* __restrict__ b1,
                                                  const float* __restrict__ w2,
                                                  const float* __restrict__ b2) {
    __shared__ float sg[LL];
    __shared__ float red[256];
    __shared__ float sh_s;
    int b = blockIdx.x;
    int tid = threadIdx.x;
    for (int i = tid; i < LL; i += 256) sg[i] = g_gm[b * LL + i];
    __syncthreads();

    float ssh = 0.f;
    for (int t = tid; t < 66 * 64; t += 256) {
        int r = t >> 6, j = t & 63;
        int rr = refl(r);
        ssh += fabsf(sg[rr * 64 + refl(j + 2)] - sg[rr * 64 + refl(j)]);
    }
    float ssv = 0.f;
    for (int t = tid; t < 64 * 66; t += 256) {
        int i = t / 66, c = t % 66;
        int cc = refl(c);
        ssv += fabsf(sg[refl(i + 2) * 64 + cc] - sg[refl(i) * 64 + cc]);
    }

    red[tid] = ssh; __syncthreads();
    for (int s = 128; s > 0; s >>= 1) { if (tid < s) red[tid] += red[tid + s]; __syncthreads(); }
    if (tid == 0) sh_s = red[0] * (1.f / 4224.f);
    __syncthreads();
    red[tid] = ssv; __syncthreads();
    for (int s = 128; s > 0; s >>= 1) { if (tid < s) red[tid] += red[tid + s]; __syncthreads(); }
    if (tid == 0) {
        float sh = sh_s, sv = red[0] * (1.f / 4224.f);
        float sc[4] = { sh, sv, 0.5f * (sh + sv), fabsf(sh - sv) };
        float hid[16];
#pragma unroll
        for (int j = 0; j < 16; j++) {
            float a = b1[j];
#pragma unroll
            for (int k = 0; k < 4; k++) a += sc[k] * w1[j * 4 + k];
            hid[j] = fmaxf(a, 0.f);
        }
        int best = 0; float bv = -1e30f;
#pragma unroll
        for (int i = 0; i < 4; i++) {
            float a = b2[i];
#pragma unroll
            for (int j = 0; j < 16; j++) a += hid[j] * w2[i * 16 + j];
            if (a > bv) { bv = a; best = i; }
        }
        g_dir[b] = best;
    }
}

// -------------------- 2b) fc2_w fp32 -> bf16 prep ----------------------------
__global__ __launch_bounds__(256) void w2cvt_kernel(const float* __restrict__ w2) {
    int i = (blockIdx.x * blockDim.x + threadIdx.x) * 4;
    if (i >= CC * DIN) return;
    float4 v = *(const float4*)(w2 + i);
    __nv_bfloat162 lo = __float22bfloat162_rn(make_float2(v.x, v.y));
    __nv_bfloat162 hi = __float22bfloat162_rn(make_float2(v.z, v.w));
    *(__nv_bfloat162*)(g_w2b + i) = lo;
    *(__nv_bfloat162*)(g_w2b + i + 2) = hi;
}

// --------------------- 3) GEMM1 (tf32 MMA, double-buffered cp.async) --------
// h1 = gather(xn) @ fc1_w^T + b1 ; BM=128 BN=192 BK=32, 384 threads (4x3 warps)
#define G1_ASZ (128 * 36)
#define G1_BSZ (192 * 36)
#define G1_TSZ (G1_ASZ + G1_BSZ)

__device__ __forceinline__ void g1_load(const float* __restrict__ xnb,
                                        const float* __restrict__ w1,
                                        int m0, int n0, int k0, int dir,
                                        int tid, float* As, float* Bs) {
#pragma unroll
    for (int i = 0; i < 3; i++) {
        int q = tid + i * 384;
        if (q < 1024) {
            int row = q >> 3, c4 = q & 7;
            int l = m0 + row;
            int pix;
            if (dir == 0)      pix = l;
            else if (dir == 3) pix = ((l & 63) << 6) + 63 - (l >> 6);
            else               pix = ((l & 63) << 6) + (l >> 6);
            cp16(&As[row * 36 + c4 * 4], xnb + (size_t)pix * CC + k0 + c4 * 4);
        }
    }
#pragma unroll
    for (int i = 0; i < 4; i++) {
        int q = tid + i * 384;
        int row = q >> 3, c4 = q & 7;
        cp16(&Bs[row * 36 + c4 * 4], w1 + (size_t)(n0 + row) * CC + k0 + c4 * 4);
    }
}

__global__ __launch_bounds__(384) void gemm1_tc(const float* __restrict__ w1,
                                                const float* __restrict__ b1) {
    extern __shared__ float sm1[];
    const int b  = blockIdx.z;
    const int m0 = blockIdx.x * 128;
    const int n0 = blockIdx.y * 192;
    const int dir = g_dir[b];
    const int tid = threadIdx.x, lane = tid & 31, wid = tid >> 5;
    const int mw = (wid & 3) * 32, nw = (wid >> 2) * 64;
    const float* xnb = g_xn + (size_t)b * LL * CC;

    float c[2][8][4];
#pragma unroll
    for (int im = 0; im < 2; im++)
#pragma unroll
        for (int jn = 0; jn < 8; jn++)
#pragma unroll
            for (int t = 0; t < 4; t++) c[im][jn][t] = 0.f;

    g1_load(xnb, w1, m0, n0, 0, dir, tid, sm1, sm1 + G1_ASZ);
    cp_commit();

    const int NS = CC / 32;   // 6
#pragma unroll 1
    for (int s = 0; s < NS; s++) {
        cp_wait0();
        __syncthreads();
        float* As = sm1 + (s & 1) * G1_TSZ;
        float* Bs = As + G1_ASZ;
        if (s + 1 < NS) {
            float* An = sm1 + ((s + 1) & 1) * G1_TSZ;
            g1_load(xnb, w1, m0, n0, (s + 1) * 32, dir, tid, An, An + G1_ASZ);
            cp_commit();
        }
#pragma unroll
        for (int kk = 0; kk < 4; kk++) {
            int kc = kk * 8 + (lane & 3);
            unsigned a[2][4];
#pragma unroll
            for (int im = 0; im < 2; im++) {
                int r = mw + im * 16 + (lane >> 2);
                a[im][0] = __float_as_uint(As[r * 36 + kc]);
                a[im][1] = __float_as_uint(As[(r + 8) * 36 + kc]);
                a[im][2] = __float_as_uint(As[r * 36 + kc + 4]);
                a[im][3] = __float_as_uint(As[(r + 8) * 36 + kc + 4]);
            }
#pragma unroll
            for (int jn = 0; jn < 8; jn++) {
                int n = nw + jn * 8 + (lane >> 2);
                unsigned b0 = __float_as_uint(Bs[n * 36 + kc]);
                unsigned b1v = __float_as_uint(Bs[n * 36 + kc + 4]);
#pragma unroll
                for (int im = 0; im < 2; im++) mma_tf32(c[im][jn], a[im], b0, b1v);
            }
        }
        __syncthreads();
    }
#pragma unroll
    for (int im = 0; im < 2; im++) {
        int r0 = m0 + mw + im * 16 + (lane >> 2);
#pragma unroll
        for (int jn = 0; jn < 8; jn++) {
            int col = n0 + nw + jn * 8 + 2 * (lane & 3);
            float bx = __ldg(b1 + col), by = __ldg(b1 + col + 1);
            __nv_bfloat162 o0 = __float22bfloat162_rn(
                make_float2(c[im][jn][0] + bx, c[im][jn][1] + by));
            __nv_bfloat162 o1 = __float22bfloat162_rn(
                make_float2(c[im][jn][2] + bx, c[im][jn][3] + by));
            *(__nv_bfloat162*)(g_h1 + ((size_t)b * LL + r0) * DIN + col) = o0;
            *(__nv_bfloat162*)(g_h1 + ((size_t)b * LL + r0 + 8) * DIN + col) = o1;
        }
    }
}

// ---------------------------- 4) depthwise conv3 + GELU (bf16 io) -----------
__device__ __forceinline__ void ld4bf(const __nv_bfloat16* p, float v[4]) {
    uint2 u = *(const uint2*)p;
    float2 a = __bfloat1622float2(*reinterpret_cast<__nv_bfloat162*>(&u.x));
    float2 b = __bfloat1622float2(*reinterpret_cast<__nv_bfloat162*>(&u.y));
    v[0] = a.x; v[1] = a.y; v[2] = b.x; v[3] = b.y;
}

__global__ __launch_bounds__(384) void convgelu_kernel(const float* __restrict__ cw,
                                                       const float* __restrict__ cb) {
    const int b  = blockIdx.y;
    const int l0 = blockIdx.x * 128;
    const int tid = threadIdx.x;
    const int d4 = tid % 96;
    const int rg = tid / 96;
    const int ls = l0 + rg * 32;
    const int d0 = d4 * 4;

    float w0[4], w1[4], w2[4], bb[4];
#pragma unroll
    for (int j = 0; j < 4; j++) {
        w0[j] = __ldg(cw + (d0 + j) * 3 + 0);
        w1[j] = __ldg(cw + (d0 + j) * 3 + 1);
        w2[j] = __ldg(cw + (d0 + j) * 3 + 2);
        bb[j] = __ldg(cb + d0 + j);
    }

    const __nv_bfloat16* base = g_h1 + ((size_t)b * LL) * DIN + d0;
    __nv_bfloat16* obase = g_act + ((size_t)b * LL) * DIN + d0;

    float pv[4] = { 0, 0, 0, 0 }, cv[4], nv[4];
    if (ls != 0) ld4bf(base + (size_t)(ls - 1) * DIN, pv);
    ld4bf(base + (size_t)ls * DIN, cv);

#pragma unroll 4
    for (int i = 0; i < 32; i++) {
        int l = ls + i;
        if (l == LL - 1) { nv[0] = nv[1] = nv[2] = nv[3] = 0.f; }
        else ld4bf(base + (size_t)(l + 1) * DIN, nv);
        float o[4];
#pragma unroll
        for (int j = 0; j < 4; j++) {
            float v = pv[j] * w0[j] + cv[j] * w1[j] + nv[j] * w2[j] + bb[j];
            o[j] = 0.5f * v * (1.f + erff(v * 0.70710678118654752f));
        }
        __nv_bfloat162 q0 = __float22bfloat162_rn(make_float2(o[0], o[1]));
        __nv_bfloat162 q1 = __float22bfloat162_rn(make_float2(o[2], o[3]));
        uint2 st;
        st.x = *reinterpret_cast<unsigned*>(&q0);
        st.y = *reinterpret_cast<unsigned*>(&q1);
        *(uint2*)(obase + (size_t)l * DIN) = st;
#pragma unroll
        for (int j = 0; j < 4; j++) { pv[j] = cv[j]; cv[j] = nv[j]; }
    }
}

// --------- 5) GEMM2 (bf16 MMA, double-buffered): out = x + act @ w2^T + b2 ---
// BM=128 BN=192 BK=32, 384 threads (12 warps, 4x3); smem as uint (bf16x2)
// Row stride 20 uints = 80 bytes (16B multiple -> cp.async-legal, conflict-free)
#define G2_AST 20
#define G2_ASZ (128 * G2_AST)
#define G2_BSZ (192 * G2_AST)
#define G2_TSZ (G2_ASZ + G2_BSZ)

__device__ __forceinline__ void g2_load(const __nv_bfloat16* __restrict__ act,
                                        const __nv_bfloat16* __restrict__ w2,
                                        int m0, int k0, int tid,
                                        unsigned* As, unsigned* Bs) {
#pragma unroll
    for (int i = 0; i < 2; i++) {
        int q = tid + i * 384;
        if (q < 512) {
            int row = q >> 2, c4 = q & 3;
            cp16(&As[row * G2_AST + c4 * 4],
                 act + (size_t)(m0 + row) * DIN + k0 + c4 * 8);
        }
    }
#pragma unroll
    for (int i = 0; i < 2; i++) {
        int q = tid + i * 384;
        int row = q >> 2, c4 = q & 3;
        cp16(&Bs[row * G2_AST + c4 * 4],
             w2 + (size_t)row * DIN + k0 + c4 * 8);
    }
}

__global__ __launch_bounds__(384) void gemm2_tc(const float* __restrict__ b2,
                                                const float* __restrict__ x,
                                                float* __restrict__ out) {
    extern __shared__ unsigned sm2[];
    const int b  = blockIdx.z;
    const int m0 = blockIdx.x * 128;
    const int tid = threadIdx.x, lane = tid & 31, wid = tid >> 5;
    const int mw = (wid & 3) * 32, nw = (wid >> 2) * 64;
    const __nv_bfloat16* act = g_act + (size_t)b * LL * DIN;

    float c[2][8][4];
#pragma unroll
    for (int im = 0; im < 2; im++)
#pragma unroll
        for (int jn = 0; jn < 8; jn++)
#pragma unroll
            for (int t = 0; t < 4; t++) c[im][jn][t] = 0.f;

    g2_load(act, g_w2b, m0, 0, tid, sm2, sm2 + G2_ASZ);
    cp_commit();

    const int NS = DIN / 32;   // 12
#pragma unroll 1
    for (int s = 0; s < NS; s++) {
        cp_wait0();
        __syncthreads();
        unsigned* As = sm2 + (s & 1) * G2_TSZ;
        unsigned* Bs = As + G2_ASZ;
        if (s + 1 < NS) {
            unsigned* An = sm2 + ((s + 1) & 1) * G2_TSZ;
            g2_load(act, g_w2b, m0, (s + 1) * 32, tid, An, An + G2_ASZ);
            cp_commit();
        }
#pragma unroll
        for (int kk = 0; kk < 2; kk++) {
            int k2 = kk * 8 + (lane & 3);
            unsigned a[2][4];
#pragma unroll
            for (int im = 0; im < 2; im++) {
                int r = mw + im * 16 + (lane >> 2);
                a[im][0] = As[r * G2_AST + k2];
                a[im][1] = As[(r + 8) * G2_AST + k2];
                a[im][2] = As[r * G2_AST + k2 + 4];
                a[im][3] = As[(r + 8) * G2_AST + k2 + 4];
            }
#pragma unroll
            for (int jn = 0; jn < 8; jn++) {
                int n = nw + jn * 8 + (lane >> 2);
                unsigned b0 = Bs[n * G2_AST + k2];
                unsigned b1v = Bs[n * G2_AST + k2 + 4];
#pragma unroll
                for (int im = 0; im < 2; im++) mma_bf16(c[im][jn], a[im], b0, b1v);
            }
        }
        __syncthreads();
    }
#pragma unroll
    for (int im = 0; im < 2; im++) {
        int r0 = m0 + mw + im * 16 + (lane >> 2);
#pragma unroll
        for (int jn = 0; jn < 8; jn++) {
            int col = nw + jn * 8 + 2 * (lane & 3);
            float bx = __ldg(b2 + col), by = __ldg(b2 + col + 1);
            size_t base0 = ((size_t)b * LL + r0) * CC + col;
            size_t base1 = ((size_t)b * LL + r0 + 8) * CC + col;
            float2 x0 = *(const float2*)(x + base0);
            float2 x1 = *(const float2*)(x + base1);
            float2 o0 = { c[im][jn][0] + bx + x0.x, c[im][jn][1] + by + x0.y };
            float2 o1 = { c[im][jn][2] + bx + x1.x, c[im][jn][3] + by + x1.y };
            *(float2*)(out + base0) = o0;
            *(float2*)(out + base1) = o1;
        }
    }
}

// ---------------------------------------------------------------------------
extern "C" void kernel_launch(void* const* d_in, const int* in_sizes, int n_in,
                              void* d_out, int out_size) {
    const float* x      = (const float*)d_in[0];
    const float* norm_w = (const float*)d_in[1];
    const float* norm_b = (const float*)d_in[2];
    const float* sel_w1 = (const float*)d_in[3];
    const float* sel_b1 = (const float*)d_in[4];
    const float* sel_w2 = (const float*)d_in[5];
    const float* sel_b2 = (const float*)d_in[6];
    const float* fc1_w  = (const float*)d_in[7];
    const float* fc1_b  = (const float*)d_in[8];
    const float* conv_w = (const float*)d_in[9];
    const float* conv_b = (const float*)d_in[10];
    const float* fc2_w  = (const float*)d_in[11];
    const float* fc2_b  = (const float*)d_in[12];
    float* out = (float*)d_out;

    cudaFuncSetAttribute(gemm1_tc, cudaFuncAttributeMaxDynamicSharedMemorySize,
                         2 * G1_TSZ * (int)sizeof(float));
    cudaFuncSetAttribute(gemm2_tc, cudaFuncAttributeMaxDynamicSharedMemorySize,
                         2 * G2_TSZ * (int)sizeof(unsigned));

    ln_kernel<<<(BB * LL) / 8, 256>>>(x, norm_w, norm_b);
    sel_kernel<<<BB, 256>>>(sel_w1, sel_b1, sel_w2, sel_b2);
    w2cvt_kernel<<<(CC * DIN / 4 + 255) / 256, 256>>>(fc2_w);
    gemm1_tc<<<dim3(LL / 128, DIN / 192, BB), 384,
               2 * G1_TSZ * sizeof(float)>>>(fc1_w, fc1_b);
    convgelu_kernel<<<dim3(LL / 128, BB), 384>>>(conv_w, conv_b);
    gemm2_tc<<<dim3(LL / 128, 1, BB), 384,
               2 * G2_TSZ * sizeof(unsigned)>>>(fc2_b, x, out);
}

// round 6
// speedup vs baseline: 4.1339x; 1.0681x over previous
#include <cuda_runtime.h>
#include <cuda_bf16.h>
#include <math.h>

#define BB   32
#define HH   64
#define WW   64
#define CC   192
#define DIN  384
#define LL   4096   // HH*WW

// ---------------- scratch (device globals; no runtime alloc) ----------------
__device__ __nv_bfloat16 g_xn [(size_t)BB * LL * CC];     // layernormed x (bf16)
__device__ float g_gm [BB * LL];                          // per-pixel mean of xn
__device__ int   g_dir[BB];                               // direction per batch
__device__ __nv_bfloat16 g_h1 [(size_t)BB * LL * DIN];    // fc1 output (bf16)
__device__ __nv_bfloat16 g_act[(size_t)BB * LL * DIN];    // gelu(conv(h1)) (bf16)
__device__ __nv_bfloat16 g_w1b[DIN * CC];                 // fc1_w in bf16
__device__ __nv_bfloat16 g_w2b[CC * DIN];                 // fc2_w in bf16

__device__ __forceinline__ void cp16(void* dst, const void* src) {
    unsigned d = (unsigned)__cvta_generic_to_shared(dst);
    asm volatile("cp.async.ca.shared.global [%0], [%1], 16;" :: "r"(d), "l"(src));
}
__device__ __forceinline__ void cp_commit() {
    asm volatile("cp.async.commit_group;");
}
__device__ __forceinline__ void cp_wait0() {
    asm volatile("cp.async.wait_group 0;");
}

__device__ __forceinline__ void mma_bf16(float c[4], const unsigned a[4],
                                         unsigned b0, unsigned b1) {
    asm volatile(
        "mma.sync.aligned.m16n8k16.row.col.f32.bf16.bf16.f32 "
        "{%0,%1,%2,%3}, {%4,%5,%6,%7}, {%8,%9}, {%0,%1,%2,%3};"
        : "+f"(c[0]), "+f"(c[1]), "+f"(c[2]), "+f"(c[3])
        : "r"(a[0]), "r"(a[1]), "r"(a[2]), "r"(a[3]), "r"(b0), "r"(b1));
}

// ---------------------------- 1) LayerNorm (bf16 out) ------------------------
// one warp per pixel; each lane handles 3 channel-pairs
__global__ __launch_bounds__(256) void ln_kernel(const float* __restrict__ x,
                                                 const float* __restrict__ nw,
                                                 const float* __restrict__ nb) {
    int warp = (blockIdx.x * blockDim.x + threadIdx.x) >> 5;
    int lane = threadIdx.x & 31;
    if (warp >= BB * LL) return;
    const float* row = x + (size_t)warp * CC;

    float2 v[3];
    float s = 0.f;
#pragma unroll
    for (int i = 0; i < 3; i++) {
        v[i] = *(const float2*)(row + 2 * lane + 64 * i);
        s += v[i].x + v[i].y;
    }
#pragma unroll
    for (int o = 16; o; o >>= 1) s += __shfl_xor_sync(0xffffffffu, s, o);
    float mu = s * (1.f / CC);

    float q = 0.f;
#pragma unroll
    for (int i = 0; i < 3; i++) {
        float dx = v[i].x - mu, dy = v[i].y - mu;
        q += dx * dx + dy * dy;
    }
#pragma unroll
    for (int o = 16; o; o >>= 1) q += __shfl_xor_sync(0xffffffffu, q, o);
    float rsig = rsqrtf(q * (1.f / CC) + 1e-5f);

    float xs = 0.f;
    __nv_bfloat16* dst = g_xn + (size_t)warp * CC;
#pragma unroll
    for (int i = 0; i < 3; i++) {
        int c = 2 * lane + 64 * i;
        float ax = (v[i].x - mu) * rsig * nw[c] + nb[c];
        float ay = (v[i].y - mu) * rsig * nw[c + 1] + nb[c + 1];
        *(__nv_bfloat162*)(dst + c) = __float22bfloat162_rn(make_float2(ax, ay));
        xs += ax + ay;
    }
#pragma unroll
    for (int o = 16; o; o >>= 1) xs += __shfl_xor_sync(0xffffffffu, xs, o);
    if (lane == 0) g_gm[warp] = xs * (1.f / CC);
}

// ---------------------------- 2) Direction selector --------------------------
__device__ __forceinline__ int refl(int k) {
    return (k == 0) ? 1 : ((k == 65) ? 62 : (k - 1));
}

__global__ __launch_bounds__(256) void sel_kernel(const float* __restrict__ w1,
                                                  const float* __restrict__ b1,
                                                  const float* __restrict__ w2,
                                                  const float* __restrict__ b2) {
    __shared__ float sg[LL];
    __shared__ float red[256];
    __shared__ float sh_s;
    int b = blockIdx.x;
    int tid = threadIdx.x;
    for (int i = tid; i < LL; i += 256) sg[i] = g_gm[b * LL + i];
    __syncthreads();

    float ssh = 0.f;
    for (int t = tid; t < 66 * 64; t += 256) {
        int r = t >> 6, j = t & 63;
        int rr = refl(r);
        ssh += fabsf(sg[rr * 64 + refl(j + 2)] - sg[rr * 64 + refl(j)]);
    }
    float ssv = 0.f;
    for (int t = tid; t < 64 * 66; t += 256) {
        int i = t / 66, c = t % 66;
        int cc = refl(c);
        ssv += fabsf(sg[refl(i + 2) * 64 + cc] - sg[refl(i) * 64 + cc]);
    }

    red[tid] = ssh; __syncthreads();
    for (int s = 128; s > 0; s >>= 1) { if (tid < s) red[tid] += red[tid + s]; __syncthreads(); }
    if (tid == 0) sh_s = red[0] * (1.f / 4224.f);
    __syncthreads();
    red[tid] = ssv; __syncthreads();
    for (int s = 128; s > 0; s >>= 1) { if (tid < s) red[tid] += red[tid + s]; __syncthreads(); }
    if (tid == 0) {
        float sh = sh_s, sv = red[0] * (1.f / 4224.f);
        float sc[4] = { sh, sv, 0.5f * (sh + sv), fabsf(sh - sv) };
        float hid[16];
#pragma unroll
        for (int j = 0; j < 16; j++) {
            float a = b1[j];
#pragma unroll
            for (int k = 0; k < 4; k++) a += sc[k] * w1[j * 4 + k];
            hid[j] = fmaxf(a, 0.f);
        }
        int best = 0; float bv = -1e30f;
#pragma unroll
        for (int i = 0; i < 4; i++) {
            float a = b2[i];
#pragma unroll
            for (int j = 0; j < 16; j++) a += hid[j] * w2[i * 16 + j];
            if (a > bv) { bv = a; best = i; }
        }
        g_dir[b] = best;
    }
}

// -------------------- 2b) weights fp32 -> bf16 prep --------------------------
__global__ __launch_bounds__(256) void wcvt_kernel(const float* __restrict__ w1,
                                                   const float* __restrict__ w2) {
    int i = (blockIdx.x * blockDim.x + threadIdx.x) * 4;
    if (i >= DIN * CC) return;   // both weights have DIN*CC elements
    {
        float4 v = *(const float4*)(w1 + i);
        *(__nv_bfloat162*)(g_w1b + i) = __float22bfloat162_rn(make_float2(v.x, v.y));
        *(__nv_bfloat162*)(g_w1b + i + 2) = __float22bfloat162_rn(make_float2(v.z, v.w));
    }
    {
        float4 v = *(const float4*)(w2 + i);
        *(__nv_bfloat162*)(g_w2b + i) = __float22bfloat162_rn(make_float2(v.x, v.y));
        *(__nv_bfloat162*)(g_w2b + i + 2) = __float22bfloat162_rn(make_float2(v.z, v.w));
    }
}

// ------------------ shared GEMM geometry: BM=128 BN=192 BK=32, 768 thr -------
// smem rows: 16 data uints (32 bf16) padded to 20; A=128 rows, B=192 rows
#define GST 20
#define GA  (128 * GST)
#define GB  (192 * GST)
#define GT  (GA + GB)

// --------------------- 3) GEMM1 (bf16 MMA): h1 = gather(xn) @ w1^T + b1 ------
__device__ __forceinline__ void g1_load(const __nv_bfloat16* __restrict__ xnb,
                                        int m0, int n0, int k0, int dir,
                                        int tid, unsigned* As, unsigned* Bs) {
    if (tid < 512) {
        int row = tid >> 2, c4 = tid & 3;
        int l = m0 + row;
        int pix;
        if (dir == 0)      pix = l;
        else if (dir == 3) pix = ((l & 63) << 6) + 63 - (l >> 6);
        else               pix = ((l & 63) << 6) + (l >> 6);
        cp16(&As[row * GST + c4 * 4], xnb + (size_t)pix * CC + k0 + c4 * 8);
    }
    {
        int row = tid >> 2, c4 = tid & 3;
        cp16(&Bs[row * GST + c4 * 4], g_w1b + (size_t)(n0 + row) * CC + k0 + c4 * 8);
    }
}

__global__ __launch_bounds__(768) void gemm1_tc(const float* __restrict__ b1) {
    extern __shared__ unsigned sm1[];
    const int b  = blockIdx.z;
    const int m0 = blockIdx.x * 128;
    const int n0 = blockIdx.y * 192;
    const int dir = g_dir[b];
    const int tid = threadIdx.x, lane = tid & 31, wid = tid >> 5;
    const int mw = (wid & 3) * 32, nw = (wid >> 2) * 32;
    const __nv_bfloat16* xnb = g_xn + (size_t)b * LL * CC;

    float c[2][4][4];
#pragma unroll
    for (int im = 0; im < 2; im++)
#pragma unroll
        for (int jn = 0; jn < 4; jn++)
#pragma unroll
            for (int t = 0; t < 4; t++) c[im][jn][t] = 0.f;

    g1_load(xnb, m0, n0, 0, dir, tid, sm1, sm1 + GA);
    cp_commit();

    const int NS = CC / 32;   // 6
#pragma unroll 1
    for (int s = 0; s < NS; s++) {
        cp_wait0();
        __syncthreads();
        unsigned* As = sm1 + (s & 1) * GT;
        unsigned* Bs = As + GA;
        if (s + 1 < NS) {
            unsigned* An = sm1 + ((s + 1) & 1) * GT;
            g1_load(xnb, m0, n0, (s + 1) * 32, dir, tid, An, An + GA);
            cp_commit();
        }
#pragma unroll
        for (int kk = 0; kk < 2; kk++) {
            int k2 = kk * 8 + (lane & 3);
            unsigned a[2][4];
#pragma unroll
            for (int im = 0; im < 2; im++) {
                int r = mw + im * 16 + (lane >> 2);
                a[im][0] = As[r * GST + k2];
                a[im][1] = As[(r + 8) * GST + k2];
                a[im][2] = As[r * GST + k2 + 4];
                a[im][3] = As[(r + 8) * GST + k2 + 4];
            }
#pragma unroll
            for (int jn = 0; jn < 4; jn++) {
                int n = nw + jn * 8 + (lane >> 2);
                unsigned b0 = Bs[n * GST + k2];
                unsigned b1v = Bs[n * GST + k2 + 4];
#pragma unroll
                for (int im = 0; im < 2; im++) mma_bf16(c[im][jn], a[im], b0, b1v);
            }
        }
        __syncthreads();
    }
#pragma unroll
    for (int im = 0; im < 2; im++) {
        int r0 = m0 + mw + im * 16 + (lane >> 2);
#pragma unroll
        for (int jn = 0; jn < 4; jn++) {
            int col = n0 + nw + jn * 8 + 2 * (lane & 3);
            float bx = __ldg(b1 + col), by = __ldg(b1 + col + 1);
            __nv_bfloat162 o0 = __float22bfloat162_rn(
                make_float2(c[im][jn][0] + bx, c[im][jn][1] + by));
            __nv_bfloat162 o1 = __float22bfloat162_rn(
                make_float2(c[im][jn][2] + bx, c[im][jn][3] + by));
            *(__nv_bfloat162*)(g_h1 + ((size_t)b * LL + r0) * DIN + col) = o0;
            *(__nv_bfloat162*)(g_h1 + ((size_t)b * LL + r0 + 8) * DIN + col) = o1;
        }
    }
}

// ---------------------------- 4) depthwise conv3 + GELU (bf16 io) -----------
__device__ __forceinline__ void ld4bf(const __nv_bfloat16* p, float v[4]) {
    uint2 u = *(const uint2*)p;
    float2 a = __bfloat1622float2(*reinterpret_cast<__nv_bfloat162*>(&u.x));
    float2 b = __bfloat1622float2(*reinterpret_cast<__nv_bfloat162*>(&u.y));
    v[0] = a.x; v[1] = a.y; v[2] = b.x; v[3] = b.y;
}

__global__ __launch_bounds__(384) void convgelu_kernel(const float* __restrict__ cw,
                                                       const float* __restrict__ cb) {
    const int b  = blockIdx.y;
    const int l0 = blockIdx.x * 128;
    const int tid = threadIdx.x;
    const int d4 = tid % 96;
    const int rg = tid / 96;
    const int ls = l0 + rg * 32;
    const int d0 = d4 * 4;

    float w0[4], w1[4], w2[4], bb[4];
#pragma unroll
    for (int j = 0; j < 4; j++) {
        w0[j] = __ldg(cw + (d0 + j) * 3 + 0);
        w1[j] = __ldg(cw + (d0 + j) * 3 + 1);
        w2[j] = __ldg(cw + (d0 + j) * 3 + 2);
        bb[j] = __ldg(cb + d0 + j);
    }

    const __nv_bfloat16* base = g_h1 + ((size_t)b * LL) * DIN + d0;
    __nv_bfloat16* obase = g_act + ((size_t)b * LL) * DIN + d0;

    float pv[4] = { 0, 0, 0, 0 }, cv[4], nv[4];
    if (ls != 0) ld4bf(base + (size_t)(ls - 1) * DIN, pv);
    ld4bf(base + (size_t)ls * DIN, cv);

#pragma unroll 4
    for (int i = 0; i < 32; i++) {
        int l = ls + i;
        if (l == LL - 1) { nv[0] = nv[1] = nv[2] = nv[3] = 0.f; }
        else ld4bf(base + (size_t)(l + 1) * DIN, nv);
        float o[4];
#pragma unroll
        for (int j = 0; j < 4; j++) {
            float v = pv[j] * w0[j] + cv[j] * w1[j] + nv[j] * w2[j] + bb[j];
            o[j] = 0.5f * v * (1.f + erff(v * 0.70710678118654752f));
        }
        __nv_bfloat162 q0 = __float22bfloat162_rn(make_float2(o[0], o[1]));
        __nv_bfloat162 q1 = __float22bfloat162_rn(make_float2(o[2], o[3]));
        uint2 st;
        st.x = *reinterpret_cast<unsigned*>(&q0);
        st.y = *reinterpret_cast<unsigned*>(&q1);
        *(uint2*)(obase + (size_t)l * DIN) = st;
#pragma unroll
        for (int j = 0; j < 4; j++) { pv[j] = cv[j]; cv[j] = nv[j]; }
    }
}

// --------- 5) GEMM2 (bf16 MMA): out = x + act @ w2^T + b2 --------------------
__device__ __forceinline__ void g2_load(const __nv_bfloat16* __restrict__ act,
                                        int m0, int k0, int tid,
                                        unsigned* As, unsigned* Bs) {
    if (tid < 512) {
        int row = tid >> 2, c4 = tid & 3;
        cp16(&As[row * GST + c4 * 4], act + (size_t)(m0 + row) * DIN + k0 + c4 * 8);
    }
    {
        int row = tid >> 2, c4 = tid & 3;
        cp16(&Bs[row * GST + c4 * 4], g_w2b + (size_t)row * DIN + k0 + c4 * 8);
    }
}

__global__ __launch_bounds__(768) void gemm2_tc(const float* __restrict__ b2,
                                                const float* __restrict__ x,
                                                float* __restrict__ out) {
    extern __shared__ unsigned sm2[];
    const int b  = blockIdx.z;
    const int m0 = blockIdx.x * 128;
    const int tid = threadIdx.x, lane = tid & 31, wid = tid >> 5;
    const int mw = (wid & 3) * 32, nw = (wid >> 2) * 32;
    const __nv_bfloat16* act = g_act + (size_t)b * LL * DIN;

    float c[2][4][4];
#pragma unroll
    for (int im = 0; im < 2; im++)
#pragma unroll
        for (int jn = 0; jn < 4; jn++)
#pragma unroll
            for (int t = 0; t < 4; t++) c[im][jn][t] = 0.f;

    g2_load(act, m0, 0, tid, sm2, sm2 + GA);
    cp_commit();

    const int NS = DIN / 32;   // 12
#pragma unroll 1
    for (int s = 0; s < NS; s++) {
        cp_wait0();
        __syncthreads();
        unsigned* As = sm2 + (s & 1) * GT;
        unsigned* Bs = As + GA;
        if (s + 1 < NS) {
            unsigned* An = sm2 + ((s + 1) & 1) * GT;
            g2_load(act, m0, (s + 1) * 32, tid, An, An + GA);
            cp_commit();
        }
#pragma unroll
        for (int kk = 0; kk < 2; kk++) {
            int k2 = kk * 8 + (lane & 3);
            unsigned a[2][4];
#pragma unroll
            for (int im = 0; im < 2; im++) {
                int r = mw + im * 16 + (lane >> 2);
                a[im][0] = As[r * GST + k2];
                a[im][1] = As[(r + 8) * GST + k2];
                a[im][2] = As[r * GST + k2 + 4];
                a[im][3] = As[(r + 8) * GST + k2 + 4];
            }
#pragma unroll
            for (int jn = 0; jn < 4; jn++) {
                int n = nw + jn * 8 + (lane >> 2);
                unsigned b0 = Bs[n * GST + k2];
                unsigned b1v = Bs[n * GST + k2 + 4];
#pragma unroll
                for (int im = 0; im < 2; im++) mma_bf16(c[im][jn], a[im], b0, b1v);
            }
        }
        __syncthreads();
    }
#pragma unroll
    for (int im = 0; im < 2; im++) {
        int r0 = m0 + mw + im * 16 + (lane >> 2);
#pragma unroll
        for (int jn = 0; jn < 4; jn++) {
            int col = nw + jn * 8 + 2 * (lane & 3);
            float bx = __ldg(b2 + col), by = __ldg(b2 + col + 1);
            size_t base0 = ((size_t)b * LL + r0) * CC + col;
            size_t base1 = ((size_t)b * LL + r0 + 8) * CC + col;
            float2 x0 = *(const float2*)(x + base0);
            float2 x1 = *(const float2*)(x + base1);
            float2 o0 = { c[im][jn][0] + bx + x0.x, c[im][jn][1] + by + x0.y };
            float2 o1 = { c[im][jn][2] + bx + x1.x, c[im][jn][3] + by + x1.y };
            *(float2*)(out + base0) = o0;
            *(float2*)(out + base1) = o1;
        }
    }
}

// ---------------------------------------------------------------------------
extern "C" void kernel_launch(void* const* d_in, const int* in_sizes, int n_in,
                              void* d_out, int out_size) {
    const float* x      = (const float*)d_in[0];
    const float* norm_w = (const float*)d_in[1];
    const float* norm_b = (const float*)d_in[2];
    const float* sel_w1 = (const float*)d_in[3];
    const float* sel_b1 = (const float*)d_in[4];
    const float* sel_w2 = (const float*)d_in[5];
    const float* sel_b2 = (const float*)d_in[6];
    const float* fc1_w  = (const float*)d_in[7];
    const float* fc1_b  = (const float*)d_in[8];
    const float* conv_w = (const float*)d_in[9];
    const float* conv_b = (const float*)d_in[10];
    const float* fc2_w  = (const float*)d_in[11];
    const float* fc2_b  = (const float*)d_in[12];
    float* out = (float*)d_out;

    cudaFuncSetAttribute(gemm1_tc, cudaFuncAttributeMaxDynamicSharedMemorySize,
                         2 * GT * (int)sizeof(unsigned));
    cudaFuncSetAttribute(gemm2_tc, cudaFuncAttributeMaxDynamicSharedMemorySize,
                         2 * GT * (int)sizeof(unsigned));

    ln_kernel<<<(BB * LL) / 8, 256>>>(x, norm_w, norm_b);
    sel_kernel<<<BB, 256>>>(sel_w1, sel_b1, sel_w2, sel_b2);
    wcvt_kernel<<<(DIN * CC / 4 + 255) / 256, 256>>>(fc1_w, fc2_w);
    gemm1_tc<<<dim3(LL / 128, DIN / 192, BB), 768,
               2 * GT * sizeof(unsigned)>>>(fc1_b);
    convgelu_kernel<<<dim3(LL / 128, BB), 384>>>(conv_w, conv_b);
    gemm2_tc<<<dim3(LL / 128, 1, BB), 768,
               2 * GT * sizeof(unsigned)>>>(fc2_b, x, out);
}

// round 7
// speedup vs baseline: 4.8337x; 1.1693x over previous
#include <cuda_runtime.h>
#include <cuda_bf16.h>
#include <math.h>

#define BB   32
#define HH   64
#define WW   64
#define CC   192
#define DIN  384
#define LL   4096   // HH*WW

// ---------------- scratch (device globals; no runtime alloc) ----------------
__device__ __nv_bfloat16 g_xn [(size_t)BB * LL * CC];     // layernormed x (bf16)
__device__ float g_gm [BB * LL];                          // per-pixel mean of xn
__device__ int   g_dir[BB];                               // direction per batch
__device__ __nv_bfloat16 g_h1 [(size_t)BB * LL * DIN];    // fc1 output (bf16)
__device__ __nv_bfloat16 g_act[(size_t)BB * LL * DIN];    // gelu(conv(h1)) (bf16)
__device__ __nv_bfloat16 g_w1b[DIN * CC];                 // fc1_w in bf16
__device__ __nv_bfloat16 g_w2b[CC * DIN];                 // fc2_w in bf16

__device__ __forceinline__ void cp16(void* dst, const void* src) {
    unsigned d = (unsigned)__cvta_generic_to_shared(dst);
    asm volatile("cp.async.ca.shared.global [%0], [%1], 16;" :: "r"(d), "l"(src));
}
__device__ __forceinline__ void cp_commit() {
    asm volatile("cp.async.commit_group;");
}
__device__ __forceinline__ void cp_wait0() {
    asm volatile("cp.async.wait_group 0;");
}

__device__ __forceinline__ void ldsm4(unsigned r[4], unsigned addr) {
    asm volatile("ldmatrix.sync.aligned.m8n8.x4.shared.b16 {%0,%1,%2,%3}, [%4];"
                 : "=r"(r[0]), "=r"(r[1]), "=r"(r[2]), "=r"(r[3]) : "r"(addr));
}

__device__ __forceinline__ void mma_bf16(float c[4], const unsigned a[4],
                                         unsigned b0, unsigned b1) {
    asm volatile(
        "mma.sync.aligned.m16n8k16.row.col.f32.bf16.bf16.f32 "
        "{%0,%1,%2,%3}, {%4,%5,%6,%7}, {%8,%9}, {%0,%1,%2,%3};"
        : "+f"(c[0]), "+f"(c[1]), "+f"(c[2]), "+f"(c[3])
        : "r"(a[0]), "r"(a[1]), "r"(a[2]), "r"(a[3]), "r"(b0), "r"(b1));
}

// ---------------------------- 1) LayerNorm (bf16 out) ------------------------
__global__ __launch_bounds__(256) void ln_kernel(const float* __restrict__ x,
                                                 const float* __restrict__ nw,
                                                 const float* __restrict__ nb) {
    int warp = (blockIdx.x * blockDim.x + threadIdx.x) >> 5;
    int lane = threadIdx.x & 31;
    if (warp >= BB * LL) return;
    const float* row = x + (size_t)warp * CC;

    float2 v[3];
    float s = 0.f;
#pragma unroll
    for (int i = 0; i < 3; i++) {
        v[i] = *(const float2*)(row + 2 * lane + 64 * i);
        s += v[i].x + v[i].y;
    }
#pragma unroll
    for (int o = 16; o; o >>= 1) s += __shfl_xor_sync(0xffffffffu, s, o);
    float mu = s * (1.f / CC);

    float q = 0.f;
#pragma unroll
    for (int i = 0; i < 3; i++) {
        float dx = v[i].x - mu, dy = v[i].y - mu;
        q += dx * dx + dy * dy;
    }
#pragma unroll
    for (int o = 16; o; o >>= 1) q += __shfl_xor_sync(0xffffffffu, q, o);
    float rsig = rsqrtf(q * (1.f / CC) + 1e-5f);

    float xs = 0.f;
    __nv_bfloat16* dst = g_xn + (size_t)warp * CC;
#pragma unroll
    for (int i = 0; i < 3; i++) {
        int c = 2 * lane + 64 * i;
        float ax = (v[i].x - mu) * rsig * nw[c] + nb[c];
        float ay = (v[i].y - mu) * rsig * nw[c + 1] + nb[c + 1];
        *(__nv_bfloat162*)(dst + c) = __float22bfloat162_rn(make_float2(ax, ay));
        xs += ax + ay;
    }
#pragma unroll
    for (int o = 16; o; o >>= 1) xs += __shfl_xor_sync(0xffffffffu, xs, o);
    if (lane == 0) g_gm[warp] = xs * (1.f / CC);
}

// ---------------------------- 2) Direction selector --------------------------
__device__ __forceinline__ int refl(int k) {
    return (k == 0) ? 1 : ((k == 65) ? 62 : (k - 1));
}

__global__ __launch_bounds__(256) void sel_kernel(const float* __restrict__ w1,
                                                  const float* __restrict__ b1,
                                                  const float* __restrict__ w2,
                                                  const float* __restrict__ b2) {
    __shared__ float sg[LL];
    __shared__ float red[256];
    __shared__ float sh_s;
    int b = blockIdx.x;
    int tid = threadIdx.x;
    for (int i = tid; i < LL; i += 256) sg[i] = g_gm[b * LL + i];
    __syncthreads();

    float ssh = 0.f;
    for (int t = tid; t < 66 * 64; t += 256) {
        int r = t >> 6, j = t & 63;
        int rr = refl(r);
        ssh += fabsf(sg[rr * 64 + refl(j + 2)] - sg[rr * 64 + refl(j)]);
    }
    float ssv = 0.f;
    for (int t = tid; t < 64 * 66; t += 256) {
        int i = t / 66, c = t % 66;
        int cc = refl(c);
        ssv += fabsf(sg[refl(i + 2) * 64 + cc] - sg[refl(i) * 64 + cc]);
    }

    red[tid] = ssh; __syncthreads();
    for (int s = 128; s > 0; s >>= 1) { if (tid < s) red[tid] += red[tid + s]; __syncthreads(); }
    if (tid == 0) sh_s = red[0] * (1.f / 4224.f);
    __syncthreads();
    red[tid] = ssv; __syncthreads();
    for (int s = 128; s > 0; s >>= 1) { if (tid < s) red[tid] += red[tid + s]; __syncthreads(); }
    if (tid == 0) {
        float sh = sh_s, sv = red[0] * (1.f / 4224.f);
        float sc[4] = { sh, sv, 0.5f * (sh + sv), fabsf(sh - sv) };
        float hid[16];
#pragma unroll
        for (int j = 0; j < 16; j++) {
            float a = b1[j];
#pragma unroll
            for (int k = 0; k < 4; k++) a += sc[k] * w1[j * 4 + k];
            hid[j] = fmaxf(a, 0.f);
        }
        int best = 0; float bv = -1e30f;
#pragma unroll
        for (int i = 0; i < 4; i++) {
            float a = b2[i];
#pragma unroll
            for (int j = 0; j < 16; j++) a += hid[j] * w2[i * 16 + j];
            if (a > bv) { bv = a; best = i; }
        }
        g_dir[b] = best;
    }
}

// -------------------- 2b) weights fp32 -> bf16 prep --------------------------
__global__ __launch_bounds__(256) void wcvt_kernel(const float* __restrict__ w1,
                                                   const float* __restrict__ w2) {
    int i = (blockIdx.x * blockDim.x + threadIdx.x) * 4;
    if (i >= DIN * CC) return;
    {
        float4 v = *(const float4*)(w1 + i);
        *(__nv_bfloat162*)(g_w1b + i) = __float22bfloat162_rn(make_float2(v.x, v.y));
        *(__nv_bfloat162*)(g_w1b + i + 2) = __float22bfloat162_rn(make_float2(v.z, v.w));
    }
    {
        float4 v = *(const float4*)(w2 + i);
        *(__nv_bfloat162*)(g_w2b + i) = __float22bfloat162_rn(make_float2(v.x, v.y));
        *(__nv_bfloat162*)(g_w2b + i + 2) = __float22bfloat162_rn(make_float2(v.z, v.w));
    }
}

// ---------------- shared GEMM geometry: BM=128 BN=192 BK=64, 768 thr ---------
// smem rows: 64 bf16 = 128B data padded to 144B (16B-aligned, ldmatrix
// conflict-free: row i starts at bank 4i mod 32)
#define GRB  144                  // bytes per smem row
#define GA_B (128 * GRB)          // A tile bytes/stage
#define GB_B (192 * GRB)          // B tile bytes/stage
#define GT_B (GA_B + GB_B)        // stage bytes (46080)

// --------------------- 3) GEMM1 (bf16 MMA): h1 = gather(xn) @ w1^T + b1 ------
__device__ __forceinline__ void g1_load(const __nv_bfloat16* __restrict__ xnb,
                                        int m0, int n0, int k0, int dir,
                                        int tid, char* smA, char* smB) {
#pragma unroll
    for (int i = 0; i < 2; i++) {
        int q = tid + i * 768;
        if (q < 1024) {
            int row = q >> 3, c8 = q & 7;
            int l = m0 + row;
            int pix;
            if (dir == 0)      pix = l;
            else if (dir == 3) pix = ((l & 63) << 6) + 63 - (l >> 6);
            else               pix = ((l & 63) << 6) + (l >> 6);
            cp16(smA + row * GRB + c8 * 16, xnb + (size_t)pix * CC + k0 + c8 * 8);
        }
    }
#pragma unroll
    for (int i = 0; i < 2; i++) {
        int q = tid + i * 768;
        int row = q >> 3, c8 = q & 7;
        cp16(smB + row * GRB + c8 * 16, g_w1b + (size_t)(n0 + row) * CC + k0 + c8 * 8);
    }
}

__global__ __launch_bounds__(768) void gemm1_tc(const float* __restrict__ b1) {
    extern __shared__ char sm1[];
    const int b  = blockIdx.z;
    const int m0 = blockIdx.x * 128;
    const int n0 = blockIdx.y * 192;
    const int dir = g_dir[b];
    const int tid = threadIdx.x, lane = tid & 31, wid = tid >> 5;
    const int mw = (wid & 3) * 32, nw = (wid >> 2) * 32;
    const __nv_bfloat16* xnb = g_xn + (size_t)b * LL * CC;
    const unsigned sbase = (unsigned)__cvta_generic_to_shared(sm1);

    // per-lane ldmatrix offsets (bytes, relative to tile base)
    const unsigned a_lo = (mw + (lane & 15)) * GRB + ((lane & 16) ? 16 : 0);
    const unsigned b_lo = (nw + (lane & 7) + ((lane & 16) ? 8 : 0)) * GRB
                          + ((lane & 8) ? 16 : 0);

    float c[2][4][4];
#pragma unroll
    for (int im = 0; im < 2; im++)
#pragma unroll
        for (int jn = 0; jn < 4; jn++)
#pragma unroll
            for (int t = 0; t < 4; t++) c[im][jn][t] = 0.f;

    g1_load(xnb, m0, n0, 0, dir, tid, sm1, sm1 + GA_B);
    cp_commit();

    const int NS = CC / 64;   // 3
#pragma unroll 1
    for (int s = 0; s < NS; s++) {
        cp_wait0();
        __syncthreads();
        unsigned Au = sbase + (s & 1) * GT_B;
        unsigned Bu = Au + GA_B;
        if (s + 1 < NS) {
            char* An = sm1 + ((s + 1) & 1) * GT_B;
            g1_load(xnb, m0, n0, (s + 1) * 64, dir, tid, An, An + GA_B);
            cp_commit();
        }
#pragma unroll
        for (int kk = 0; kk < 4; kk++) {
            unsigned af[2][4], bf[2][4];
            ldsm4(af[0], Au + a_lo + kk * 32);
            ldsm4(af[1], Au + a_lo + 16 * GRB + kk * 32);
            ldsm4(bf[0], Bu + b_lo + kk * 32);
            ldsm4(bf[1], Bu + b_lo + 16 * GRB + kk * 32);
#pragma unroll
            for (int im = 0; im < 2; im++)
#pragma unroll
                for (int jn = 0; jn < 4; jn++)
                    mma_bf16(c[im][jn], af[im],
                             bf[jn >> 1][(jn & 1) * 2], bf[jn >> 1][(jn & 1) * 2 + 1]);
        }
    }
#pragma unroll
    for (int im = 0; im < 2; im++) {
        int r0 = m0 + mw + im * 16 + (lane >> 2);
#pragma unroll
        for (int jn = 0; jn < 4; jn++) {
            int col = n0 + nw + jn * 8 + 2 * (lane & 3);
            float bx = __ldg(b1 + col), by = __ldg(b1 + col + 1);
            __nv_bfloat162 o0 = __float22bfloat162_rn(
                make_float2(c[im][jn][0] + bx, c[im][jn][1] + by));
            __nv_bfloat162 o1 = __float22bfloat162_rn(
                make_float2(c[im][jn][2] + bx, c[im][jn][3] + by));
            *(__nv_bfloat162*)(g_h1 + ((size_t)b * LL + r0) * DIN + col) = o0;
            *(__nv_bfloat162*)(g_h1 + ((size_t)b * LL + r0 + 8) * DIN + col) = o1;
        }
    }
}

// ---------------------------- 4) depthwise conv3 + GELU (bf16 io) -----------
__device__ __forceinline__ void ld4bf(const __nv_bfloat16* p, float v[4]) {
    uint2 u = *(const uint2*)p;
    float2 a = __bfloat1622float2(*reinterpret_cast<__nv_bfloat162*>(&u.x));
    float2 b = __bfloat1622float2(*reinterpret_cast<__nv_bfloat162*>(&u.y));
    v[0] = a.x; v[1] = a.y; v[2] = b.x; v[3] = b.y;
}

__global__ __launch_bounds__(384) void convgelu_kernel(const float* __restrict__ cw,
                                                       const float* __restrict__ cb) {
    const int b  = blockIdx.y;
    const int l0 = blockIdx.x * 128;
    const int tid = threadIdx.x;
    const int d4 = tid % 96;
    const int rg = tid / 96;
    const int ls = l0 + rg * 32;
    const int d0 = d4 * 4;

    float w0[4], w1[4], w2[4], bb[4];
#pragma unroll
    for (int j = 0; j < 4; j++) {
        w0[j] = __ldg(cw + (d0 + j) * 3 + 0);
        w1[j] = __ldg(cw + (d0 + j) * 3 + 1);
        w2[j] = __ldg(cw + (d0 + j) * 3 + 2);
        bb[j] = __ldg(cb + d0 + j);
    }

    const __nv_bfloat16* base = g_h1 + ((size_t)b * LL) * DIN + d0;
    __nv_bfloat16* obase = g_act + ((size_t)b * LL) * DIN + d0;

    float pv[4] = { 0, 0, 0, 0 }, cv[4], nv[4];
    if (ls != 0) ld4bf(base + (size_t)(ls - 1) * DIN, pv);
    ld4bf(base + (size_t)ls * DIN, cv);

#pragma unroll 4
    for (int i = 0; i < 32; i++) {
        int l = ls + i;
        if (l == LL - 1) { nv[0] = nv[1] = nv[2] = nv[3] = 0.f; }
        else ld4bf(base + (size_t)(l + 1) * DIN, nv);
        float o[4];
#pragma unroll
        for (int j = 0; j < 4; j++) {
            float v = pv[j] * w0[j] + cv[j] * w1[j] + nv[j] * w2[j] + bb[j];
            o[j] = 0.5f * v * (1.f + erff(v * 0.70710678118654752f));
        }
        __nv_bfloat162 q0 = __float22bfloat162_rn(make_float2(o[0], o[1]));
        __nv_bfloat162 q1 = __float22bfloat162_rn(make_float2(o[2], o[3]));
        uint2 st;
        st.x = *reinterpret_cast<unsigned*>(&q0);
        st.y = *reinterpret_cast<unsigned*>(&q1);
        *(uint2*)(obase + (size_t)l * DIN) = st;
#pragma unroll
        for (int j = 0; j < 4; j++) { pv[j] = cv[j]; cv[j] = nv[j]; }
    }
}

// --------- 5) GEMM2 (bf16 MMA): out = x + act @ w2^T + b2 --------------------
__device__ __forceinline__ void g2_load(const __nv_bfloat16* __restrict__ act,
                                        int m0, int k0, int tid,
                                        char* smA, char* smB) {
#pragma unroll
    for (int i = 0; i < 2; i++) {
        int q = tid + i * 768;
        if (q < 1024) {
            int row = q >> 3, c8 = q & 7;
            cp16(smA + row * GRB + c8 * 16,
                 act + (size_t)(m0 + row) * DIN + k0 + c8 * 8);
        }
    }
#pragma unroll
    for (int i = 0; i < 2; i++) {
        int q = tid + i * 768;
        int row = q >> 3, c8 = q & 7;
        cp16(smB + row * GRB + c8 * 16, g_w2b + (size_t)row * DIN + k0 + c8 * 8);
    }
}

__global__ __launch_bounds__(768) void gemm2_tc(const float* __restrict__ b2,
                                                const float* __restrict__ x,
                                                float* __restrict__ out) {
    extern __shared__ char sm2[];
    const int b  = blockIdx.z;
    const int m0 = blockIdx.x * 128;
    const int tid = threadIdx.x, lane = tid & 31, wid = tid >> 5;
    const int mw = (wid & 3) * 32, nw = (wid >> 2) * 32;
    const __nv_bfloat16* act = g_act + (size_t)b * LL * DIN;
    const unsigned sbase = (unsigned)__cvta_generic_to_shared(sm2);

    const unsigned a_lo = (mw + (lane & 15)) * GRB + ((lane & 16) ? 16 : 0);
    const unsigned b_lo = (nw + (lane & 7) + ((lane & 16) ? 8 : 0)) * GRB
                          + ((lane & 8) ? 16 : 0);

    float c[2][4][4];
#pragma unroll
    for (int im = 0; im < 2; im++)
#pragma unroll
        for (int jn = 0; jn < 4; jn++)
#pragma unroll
            for (int t = 0; t < 4; t++) c[im][jn][t] = 0.f;

    g2_load(act, m0, 0, tid, sm2, sm2 + GA_B);
    cp_commit();

    const int NS = DIN / 64;   // 6
#pragma unroll 1
    for (int s = 0; s < NS; s++) {
        cp_wait0();
        __syncthreads();
        unsigned Au = sbase + (s & 1) * GT_B;
        unsigned Bu = Au + GA_B;
        if (s + 1 < NS) {
            char* An = sm2 + ((s + 1) & 1) * GT_B;
            g2_load(act, m0, (s + 1) * 64, tid, An, An + GA_B);
            cp_commit();
        }
#pragma unroll
        for (int kk = 0; kk < 4; kk++) {
            unsigned af[2][4], bf[2][4];
            ldsm4(af[0], Au + a_lo + kk * 32);
            ldsm4(af[1], Au + a_lo + 16 * GRB + kk * 32);
            ldsm4(bf[0], Bu + b_lo + kk * 32);
            ldsm4(bf[1], Bu + b_lo + 16 * GRB + kk * 32);
#pragma unroll
            for (int im = 0; im < 2; im++)
#pragma unroll
                for (int jn = 0; jn < 4; jn++)
                    mma_bf16(c[im][jn], af[im],
                             bf[jn >> 1][(jn & 1) * 2], bf[jn >> 1][(jn & 1) * 2 + 1]);
        }
    }
#pragma unroll
    for (int im = 0; im < 2; im++) {
        int r0 = m0 + mw + im * 16 + (lane >> 2);
#pragma unroll
        for (int jn = 0; jn < 4; jn++) {
            int col = nw + jn * 8 + 2 * (lane & 3);
            float bx = __ldg(b2 + col), by = __ldg(b2 + col + 1);
            size_t base0 = ((size_t)b * LL + r0) * CC + col;
            size_t base1 = ((size_t)b * LL + r0 + 8) * CC + col;
            float2 x0 = *(const float2*)(x + base0);
            float2 x1 = *(const float2*)(x + base1);
            float2 o0 = { c[im][jn][0] + bx + x0.x, c[im][jn][1] + by + x0.y };
            float2 o1 = { c[im][jn][2] + bx + x1.x, c[im][jn][3] + by + x1.y };
            *(float2*)(out + base0) = o0;
            *(float2*)(out + base1) = o1;
        }
    }
}

// ---------------------------------------------------------------------------
extern "C" void kernel_launch(void* const* d_in, const int* in_sizes, int n_in,
                              void* d_out, int out_size) {
    const float* x      = (const float*)d_in[0];
    const float* norm_w = (const float*)d_in[1];
    const float* norm_b = (const float*)d_in[2];
    const float* sel_w1 = (const float*)d_in[3];
    const float* sel_b1 = (const float*)d_in[4];
    const float* sel_w2 = (const float*)d_in[5];
    const float* sel_b2 = (const float*)d_in[6];
    const float* fc1_w  = (const float*)d_in[7];
    const float* fc1_b  = (const float*)d_in[8];
    const float* conv_w = (const float*)d_in[9];
    const float* conv_b = (const float*)d_in[10];
    const float* fc2_w  = (const float*)d_in[11];
    const float* fc2_b  = (const float*)d_in[12];
    float* out = (float*)d_out;

    cudaFuncSetAttribute(gemm1_tc, cudaFuncAttributeMaxDynamicSharedMemorySize,
                         2 * GT_B);
    cudaFuncSetAttribute(gemm2_tc, cudaFuncAttributeMaxDynamicSharedMemorySize,
                         2 * GT_B);

    ln_kernel<<<(BB * LL) / 8, 256>>>(x, norm_w, norm_b);
    sel_kernel<<<BB, 256>>>(sel_w1, sel_b1, sel_w2, sel_b2);
    wcvt_kernel<<<(DIN * CC / 4 + 255) / 256, 256>>>(fc1_w, fc2_w);
    gemm1_tc<<<dim3(LL / 128, DIN / 192, BB), 768, 2 * GT_B>>>(fc1_b);
    convgelu_kernel<<<dim3(LL / 128, BB), 384>>>(conv_w, conv_b);
    gemm2_tc<<<dim3(LL / 128, 1, BB), 768, 2 * GT_B>>>(fc2_b, x, out);
}